// round 3
// baseline (speedup 1.0000x reference)
#include <cuda_runtime.h>
#include <math.h>

// ---------------------------------------------------------------------------
// Problem shape (fixed): B=128, T=32, V=64, D=512, score is [128][128].
// Pipeline:
//   prep_kernel:        resolve ambiguous inputs ON DEVICE (dtype-width
//                       agnostic), masks + masked-softmax weights (wA, wB)
//   gemm_score_kernel:  fused 128x128x512 fp32 GEMM tile + per-(a,b) max
//                       reductions + weighted sums -> score[a][b]
//   loss_kernel:        /temp, row+col log-softmax diagonals, mean -> scalar
//
// Input binding: host maps by size rank; equal-size pairs ({tokens,wtA},
// {wtB,vmask}) disambiguated on device from bit patterns. Integer arrays may
// be stored as int32 (harness cast) or int64 (original dtype) — detected and
// indexed accordingly. Deterministic; graph-capturable.
// ---------------------------------------------------------------------------

#define NEG_BIG (-3.0e38f)

__device__ float g_mA[128 * 32];      // text mask as float
__device__ float g_mB[128 * 64];      // video mask as float
__device__ float g_wA[128 * 32];      // softmax token weights
__device__ float g_wB[128 * 64];      // softmax frame weights
__device__ float g_score[128 * 128];  // fine-grained similarity matrix

// Token ids < 30522: every u32 word (int32 values, or int64 low/high words)
// is < 1e5. Normal nonzero floats have bits >= 0x00800000 or the sign bit.
__device__ __forceinline__ bool looks_like_int_small(const unsigned* w, unsigned limit) {
    bool ok = true;
    #pragma unroll
    for (int i = 0; i < 8; i++) ok = ok && (w[i] <= limit);
    return ok;
}
// Integer array stored as int64 (values < 2^32) => odd (high) words are 0.
// int32 tokens/mask-of-ones have nonzero odd words.
__device__ __forceinline__ bool int_width64(const unsigned* w) {
    return (w[1] == 0u) && (w[3] == 0u) && (w[5] == 0u) && (w[7] == 0u);
}
__device__ __forceinline__ bool int_elem_nonzero(const unsigned* w, int i, bool w64) {
    return w64 ? ((w[2 * i] | w[2 * i + 1]) != 0u) : (w[i] != 0u);
}

// ---------------------------------------------------------------------------
// prep: blocks 0..127 handle wA row a (32 elems, warp 0); blocks 128..255
// handle wB row b (64 elems, 2 warps + tiny shared combine).
// q0/q1: the two "4096-elem" inputs (tokens / wtA, unknown order)
// r0/r1: the two "8192-elem" inputs (wtB / vmask, unknown order)
// ---------------------------------------------------------------------------
__global__ void prep_kernel(const void* q0, const void* q1,
                            const void* r0, const void* r1) {
    // redundant per-block resolution (uniform, cheap)
    bool q0_tok = looks_like_int_small((const unsigned*)q0, 99999u);
    const unsigned* tokw = (const unsigned*)(q0_tok ? q0 : q1);
    const float*    wtA  = (const float*)(q0_tok ? q1 : q0);
    bool tok64 = int_width64(tokw);

    bool r0_msk = looks_like_int_small((const unsigned*)r0, 1u);
    const unsigned* mskw = (const unsigned*)(r0_msk ? r0 : r1);
    const float*    wtB  = (const float*)(r0_msk ? r1 : r0);
    bool msk64 = int_width64(mskw);

    int blk = blockIdx.x;
    int t = threadIdx.x;
    if (blk < 128) {
        int a = blk;
        if (t < 32) {  // entire warp 0 takes this branch
            float m = int_elem_nonzero(tokw, a * 32 + t, tok64) ? 1.f : 0.f;
            g_mA[a * 32 + t] = m;
            float w = (m > 0.f) ? wtA[a * 32 + t] : NEG_BIG;
            float mx = w;
            #pragma unroll
            for (int o = 16; o; o >>= 1) mx = fmaxf(mx, __shfl_xor_sync(0xffffffffu, mx, o));
            float e = expf(w - mx);
            float s = e;
            #pragma unroll
            for (int o = 16; o; o >>= 1) s += __shfl_xor_sync(0xffffffffu, s, o);
            g_wA[a * 32 + t] = e / s;
        }
    } else {
        int b = blk - 128;
        __shared__ float sred[2];
        float m = int_elem_nonzero(mskw, b * 64 + t, msk64) ? 1.f : 0.f;
        g_mB[b * 64 + t] = m;
        float w = (m > 0.f) ? wtB[b * 64 + t] : NEG_BIG;
        int lane = t & 31, wp = t >> 5;
        float mx = w;
        #pragma unroll
        for (int o = 16; o; o >>= 1) mx = fmaxf(mx, __shfl_xor_sync(0xffffffffu, mx, o));
        if (lane == 0) sred[wp] = mx;
        __syncthreads();
        mx = fmaxf(sred[0], sred[1]);
        __syncthreads();
        float e = expf(w - mx);
        float s = e;
        #pragma unroll
        for (int o = 16; o; o >>= 1) s += __shfl_xor_sync(0xffffffffu, s, o);
        if (lane == 0) sred[wp] = s;
        __syncthreads();
        s = sred[0] + sred[1];
        g_wB[b * 64 + t] = e / s;
    }
}

// ---------------------------------------------------------------------------
// Fused GEMM + reductions.
// Tile: BM=BN=128, BK=16, 256 threads (tx 0..15, ty 0..15), 8x8 per thread.
// Per-thread rows: {ty*4+i} i<4 (lower 64) and {64+ty*4+i} (upper 64).
// Per-thread cols: {tx*4+j} j<4 (video-b half 0) and {64+tx*4+j} (half 1).
// Masking: A rows / B rows scaled by mask at smem-store time (== masking logits).
// ---------------------------------------------------------------------------
__global__ void __launch_bounds__(256)
gemm_score_kernel(const float* __restrict__ A, const float* __restrict__ B) {
    __shared__ __align__(16) float sh[8960];
    float* As = sh;          // [2][16][128]
    float* Bs = sh + 4096;   // [2][16][128]

    int tid = threadIdx.x;
    int tx = tid & 15, ty = tid >> 4;
    int m0 = blockIdx.y * 128, n0 = blockIdx.x * 128;

    // global-load assignment: 2 threads per tile-row, 8 floats (2 float4) each
    int lrow = tid >> 1;
    int lcb = (tid & 1) * 8;  // 0 or 8 within the 16-wide K chunk

    const float* Ap = A + (m0 + lrow) * 512 + lcb;
    const float* Bp = B + (n0 + lrow) * 512 + lcb;
    float maskAr = g_mA[m0 + lrow];
    float maskBr = g_mB[n0 + lrow];

    float c[8][8];
    #pragma unroll
    for (int i = 0; i < 8; i++)
        #pragma unroll
        for (int j = 0; j < 8; j++) c[i][j] = 0.f;

    // prologue: stage chunk 0
    float4 aS0 = *(const float4*)(Ap);
    float4 aS1 = *(const float4*)(Ap + 4);
    float4 bS0 = *(const float4*)(Bp);
    float4 bS1 = *(const float4*)(Bp + 4);

    for (int ck = 0; ck < 32; ck++) {
        float* Ad = As + (ck & 1) * 2048;
        float* Bd = Bs + (ck & 1) * 2048;
        Ad[(lcb + 0) * 128 + lrow] = aS0.x * maskAr;
        Ad[(lcb + 1) * 128 + lrow] = aS0.y * maskAr;
        Ad[(lcb + 2) * 128 + lrow] = aS0.z * maskAr;
        Ad[(lcb + 3) * 128 + lrow] = aS0.w * maskAr;
        Ad[(lcb + 4) * 128 + lrow] = aS1.x * maskAr;
        Ad[(lcb + 5) * 128 + lrow] = aS1.y * maskAr;
        Ad[(lcb + 6) * 128 + lrow] = aS1.z * maskAr;
        Ad[(lcb + 7) * 128 + lrow] = aS1.w * maskAr;
        Bd[(lcb + 0) * 128 + lrow] = bS0.x * maskBr;
        Bd[(lcb + 1) * 128 + lrow] = bS0.y * maskBr;
        Bd[(lcb + 2) * 128 + lrow] = bS0.z * maskBr;
        Bd[(lcb + 3) * 128 + lrow] = bS0.w * maskBr;
        Bd[(lcb + 4) * 128 + lrow] = bS1.x * maskBr;
        Bd[(lcb + 5) * 128 + lrow] = bS1.y * maskBr;
        Bd[(lcb + 6) * 128 + lrow] = bS1.z * maskBr;
        Bd[(lcb + 7) * 128 + lrow] = bS1.w * maskBr;
        __syncthreads();
        if (ck < 31) {  // prefetch next chunk into staging regs
            const float* Ap2 = Ap + (ck + 1) * 16;
            aS0 = *(const float4*)(Ap2);
            aS1 = *(const float4*)(Ap2 + 4);
            const float* Bp2 = Bp + (ck + 1) * 16;
            bS0 = *(const float4*)(Bp2);
            bS1 = *(const float4*)(Bp2 + 4);
        }
        #pragma unroll
        for (int kk = 0; kk < 16; kk++) {
            const float* Ac = Ad + kk * 128;
            const float* Bc = Bd + kk * 128;
            float4 a0 = *(const float4*)(Ac + ty * 4);
            float4 a1 = *(const float4*)(Ac + 64 + ty * 4);
            float4 b0 = *(const float4*)(Bc + tx * 4);
            float4 b1 = *(const float4*)(Bc + 64 + tx * 4);
            float af[8] = {a0.x, a0.y, a0.z, a0.w, a1.x, a1.y, a1.z, a1.w};
            float bf[8] = {b0.x, b0.y, b0.z, b0.w, b1.x, b1.y, b1.z, b1.w};
            #pragma unroll
            for (int i = 0; i < 8; i++)
                #pragma unroll
                for (int j = 0; j < 8; j++)
                    c[i][j] = fmaf(af[i], bf[j], c[i][j]);
        }
    }
    __syncthreads();  // done with GEMM smem; reuse for reductions

    float* redRow   = sh;         // [128 rows][2 bh * 16 tx]       = 4096
    float* redColLo = sh + 4096;  // [128 cols][16 ty] (rows < 64)  = 2048
    float* redColHi = sh + 6144;  // [128 cols][16 ty] (rows >= 64) = 2048
    float* rowmaxS  = sh + 8192;  // [128 rows][2 b-half]           = 256
    float* colmaxS  = sh + 8448;  // [128 cols][4 a-quarter]        = 512

    #pragma unroll
    for (int ii = 0; ii < 8; ii++) {
        int row = (ii < 4) ? (ty * 4 + ii) : (64 + ty * 4 + ii - 4);
        float r0 = fmaxf(fmaxf(c[ii][0], c[ii][1]), fmaxf(c[ii][2], c[ii][3]));
        float r1 = fmaxf(fmaxf(c[ii][4], c[ii][5]), fmaxf(c[ii][6], c[ii][7]));
        redRow[row * 32 + tx] = r0;
        redRow[row * 32 + 16 + tx] = r1;
    }
    #pragma unroll
    for (int jj = 0; jj < 8; jj++) {
        int col = (jj < 4) ? (tx * 4 + jj) : (64 + tx * 4 + jj - 4);
        float lo = fmaxf(fmaxf(c[0][jj], c[1][jj]), fmaxf(c[2][jj], c[3][jj]));
        float hi = fmaxf(fmaxf(c[4][jj], c[5][jj]), fmaxf(c[6][jj], c[7][jj]));
        redColLo[col * 16 + ty] = lo;
        redColHi[col * 16 + ty] = hi;
    }
    __syncthreads();

    {
        int row = tid >> 1, bh = tid & 1;
        float m = NEG_BIG;
        #pragma unroll
        for (int k = 0; k < 16; k++) m = fmaxf(m, redRow[row * 32 + bh * 16 + k]);
        rowmaxS[row * 2 + bh] = m;
    }
    for (int e = tid; e < 512; e += 256) {
        int col = e >> 2, aa = e & 3;
        const float* src = (aa < 2) ? redColLo : redColHi;
        int g = (aa & 1) * 8;
        float m = NEG_BIG;
        #pragma unroll
        for (int k = 0; k < 8; k++) m = fmaxf(m, src[col * 16 + g + k]);
        colmaxS[col * 4 + aa] = m;
    }
    __syncthreads();

    // 8 (a,b) pairs, one warp each: weighted sums + score
    {
        int wp = tid >> 5, lane = tid & 31;
        int ai = wp >> 1, bi = wp & 1;
        int a = blockIdx.y * 4 + ai;
        int b = blockIdx.x * 2 + bi;
        float val = rowmaxS[(ai * 32 + lane) * 2 + bi] * g_wA[a * 32 + lane];
        val += colmaxS[(bi * 64 + lane) * 4 + ai] * g_wB[b * 64 + lane];
        val += colmaxS[(bi * 64 + lane + 32) * 4 + ai] * g_wB[b * 64 + lane + 32];
        #pragma unroll
        for (int o = 16; o; o >>= 1) val += __shfl_xor_sync(0xffffffffu, val, o);
        if (lane == 0) g_score[a * 128 + b] = 0.5f * val;
    }
}

// ---------------------------------------------------------------------------
// loss: one CTA; threads 0..127 -> row log-softmax, 128..255 -> col.
// ---------------------------------------------------------------------------
__global__ void loss_kernel(const float* __restrict__ temp, float* __restrict__ out) {
    __shared__ float red[256];
    int tid = threadIdx.x;
    float invT = 1.0f / temp[0];
    int i = tid & 127;
    bool isRow = tid < 128;
    float mx = NEG_BIG;
    for (int j = 0; j < 128; j++) {
        float x = (isRow ? g_score[i * 128 + j] : g_score[j * 128 + i]) * invT;
        mx = fmaxf(mx, x);
    }
    float s = 0.f;
    for (int j = 0; j < 128; j++) {
        float x = (isRow ? g_score[i * 128 + j] : g_score[j * 128 + i]) * invT;
        s += expf(x - mx);
    }
    float lse = mx + logf(s);
    float diag = g_score[i * 128 + i] * invT;
    red[tid] = lse - diag;
    __syncthreads();
    for (int o = 128; o; o >>= 1) {
        if (tid < o) red[tid] += red[tid + o];
        __syncthreads();
    }
    if (tid == 0) out[0] = red[0] / 256.f;
}

// ---------------------------------------------------------------------------
// Host: bind inputs by SIZE RANK (robust to element-count vs byte-count and
// any metadata ordering). Ascending:
//   [0] temp   [1],[2] {tokens, wtA}   [3],[4] {wtB, vmask}
//   [5] featA (128*32*512)   [6] featB (128*64*512)
// (Pair grouping verified to hold for all int32/int64 storage combinations
// under both element-count and byte-count in_sizes.)
// ---------------------------------------------------------------------------
extern "C" void kernel_launch(void* const* d_in, const int* in_sizes, int n_in,
                              void* d_out, int out_size) {
    (void)out_size;
    int order[7];
    for (int i = 0; i < 7 && i < n_in; i++) order[i] = i;
    for (int i = 1; i < 7; i++) {  // stable insertion sort by size
        int o = order[i];
        long long s = in_sizes[o];
        int j = i - 1;
        while (j >= 0 && (long long)in_sizes[order[j]] > s) { order[j + 1] = order[j]; j--; }
        order[j + 1] = o;
    }
    const float* temp  = (const float*)d_in[order[0]];
    const void*  q0    = d_in[order[1]];   // tokens or wtA
    const void*  q1    = d_in[order[2]];
    const void*  r0    = d_in[order[3]];   // wtB or vmask
    const void*  r1    = d_in[order[4]];
    const float* featA = (const float*)d_in[order[5]];
    const float* featB = (const float*)d_in[order[6]];
    float* out = (float*)d_out;

    prep_kernel<<<256, 64>>>(q0, q1, r0, r1);
    gemm_score_kernel<<<dim3(64, 32), 256>>>(featA, featB);
    loss_kernel<<<1, 256>>>(temp, out);
}

// round 5
// speedup vs baseline: 2.5003x; 2.5003x over previous
#include <cuda_runtime.h>
#include <cuda_bf16.h>
#include <math.h>
#include <stdint.h>

// ---------------------------------------------------------------------------
// B=128, T=32, V=64, D=512.  score[128][128].
// sm_100 BASELINE target (no 'a' features!): mma.sync bf16 + cp.async + ldmatrix.
// Pipeline:
//   prep_kernel:    resolve ambiguous inputs, masked-softmax weights wA/wB
//   convert_kernel: fp32 -> masked bf16 hi/lo split arrays
//   gemm_kernel:    128x128 tile, 8 warps, m16n8k16 bf16 3-term split GEMM,
//                   fused row/col-max + weighted reductions -> score[a][b]
//   loss_kernel:    /temp, row+col log-softmax diagonals, mean -> scalar
// ---------------------------------------------------------------------------

#define NEG_BIG (-3.0e38f)

__device__ float g_wA[128 * 32];
__device__ float g_wB[128 * 64];
__device__ float g_score[128 * 128];

// split arrays (bf16): A [4096][512], B [8192][512]
__device__ __nv_bfloat16 g_Ahi[4096 * 512];
__device__ __nv_bfloat16 g_Alo[4096 * 512];
__device__ __nv_bfloat16 g_Bhi[8192 * 512];
__device__ __nv_bfloat16 g_Blo[8192 * 512];

// ---------------- PTX helpers (sm_80-baseline only) ----------------
__device__ __forceinline__ uint32_t smem_u32(const void* p) {
    uint32_t a;
    asm("{ .reg .u64 t; cvta.to.shared.u64 t, %1; cvt.u32.u64 %0, t; }" : "=r"(a) : "l"(p));
    return a;
}
#define CP_ASYNC16(dst, src) asm volatile("cp.async.cg.shared.global [%0], [%1], 16;" :: "r"(dst), "l"(src))
#define CP_COMMIT()          asm volatile("cp.async.commit_group;" ::: "memory")
#define CP_WAIT1()           asm volatile("cp.async.wait_group 1;" ::: "memory")
#define CP_WAIT0()           asm volatile("cp.async.wait_group 0;" ::: "memory")
#define LDSM_X4(r0, r1, r2, r3, addr) \
    asm volatile("ldmatrix.sync.aligned.m8n8.x4.shared.b16 {%0,%1,%2,%3}, [%4];" \
        : "=r"(r0), "=r"(r1), "=r"(r2), "=r"(r3) : "r"(addr))
#define MMA_BF16(d, a, b0, b1) \
    asm volatile("mma.sync.aligned.m16n8k16.row.col.f32.bf16.bf16.f32 " \
        "{%0,%1,%2,%3}, {%4,%5,%6,%7}, {%8,%9}, {%0,%1,%2,%3};" \
        : "+f"((d)[0]), "+f"((d)[1]), "+f"((d)[2]), "+f"((d)[3]) \
        : "r"((a)[0]), "r"((a)[1]), "r"((a)[2]), "r"((a)[3]), "r"(b0), "r"(b1))

// ---------------- input disambiguation ----------------
__device__ __forceinline__ bool looks_like_int_small(const unsigned* w, unsigned limit) {
    bool ok = true;
    #pragma unroll
    for (int i = 0; i < 8; i++) ok = ok && (w[i] <= limit);
    return ok;
}
__device__ __forceinline__ bool int_width64(const unsigned* w) {
    return (w[1] == 0u) && (w[3] == 0u) && (w[5] == 0u) && (w[7] == 0u);
}
__device__ __forceinline__ bool int_elem_nonzero(const unsigned* w, int i, bool w64) {
    return w64 ? ((w[2 * i] | w[2 * i + 1]) != 0u) : (w[i] != 0u);
}

// ---------------------------------------------------------------------------
// prep: softmax weights wA, wB (masked)
// ---------------------------------------------------------------------------
__global__ void prep_kernel(const void* q0, const void* q1,
                            const void* r0, const void* r1) {
    bool q0_tok = looks_like_int_small((const unsigned*)q0, 99999u);
    const unsigned* tokw = (const unsigned*)(q0_tok ? q0 : q1);
    const float*    wtA  = (const float*)(q0_tok ? q1 : q0);
    bool tok64 = int_width64(tokw);
    bool r0_msk = looks_like_int_small((const unsigned*)r0, 1u);
    const unsigned* mskw = (const unsigned*)(r0_msk ? r0 : r1);
    const float*    wtB  = (const float*)(r0_msk ? r1 : r0);
    bool msk64 = int_width64(mskw);

    int blk = blockIdx.x, t = threadIdx.x;
    if (blk < 128) {
        int a = blk;
        if (t < 32) {
            float m = int_elem_nonzero(tokw, a * 32 + t, tok64) ? 1.f : 0.f;
            float w = (m > 0.f) ? wtA[a * 32 + t] : NEG_BIG;
            float mx = w;
            #pragma unroll
            for (int o = 16; o; o >>= 1) mx = fmaxf(mx, __shfl_xor_sync(0xffffffffu, mx, o));
            float e = expf(w - mx), s = e;
            #pragma unroll
            for (int o = 16; o; o >>= 1) s += __shfl_xor_sync(0xffffffffu, s, o);
            g_wA[a * 32 + t] = e / s;
        }
    } else {
        int b = blk - 128;
        __shared__ float sred[2];
        float m = int_elem_nonzero(mskw, b * 64 + t, msk64) ? 1.f : 0.f;
        float w = (m > 0.f) ? wtB[b * 64 + t] : NEG_BIG;
        int lane = t & 31, wp = t >> 5;
        float mx = w;
        #pragma unroll
        for (int o = 16; o; o >>= 1) mx = fmaxf(mx, __shfl_xor_sync(0xffffffffu, mx, o));
        if (lane == 0) sred[wp] = mx;
        __syncthreads();
        mx = fmaxf(sred[0], sred[1]);
        __syncthreads();
        float e = expf(w - mx), s = e;
        #pragma unroll
        for (int o = 16; o; o >>= 1) s += __shfl_xor_sync(0xffffffffu, s, o);
        if (lane == 0) sred[wp] = s;
        __syncthreads();
        s = sred[0] + sred[1];
        g_wB[b * 64 + t] = e / s;
    }
}

// ---------------------------------------------------------------------------
// convert: fp32 -> masked bf16 hi/lo.
// ---------------------------------------------------------------------------
__global__ void __launch_bounds__(256)
convert_kernel(const float* __restrict__ A, const float* __restrict__ B,
               const void* q0, const void* q1, const void* r0, const void* r1) {
    bool q0_tok = looks_like_int_small((const unsigned*)q0, 99999u);
    const unsigned* tokw = (const unsigned*)(q0_tok ? q0 : q1);
    bool tok64 = int_width64(tokw);
    bool r0_msk = looks_like_int_small((const unsigned*)r0, 1u);
    const unsigned* mskw = (const unsigned*)(r0_msk ? r0 : r1);
    bool msk64 = int_width64(mskw);

    const int A_E = 4096 * 512;
    const int TOT4 = (A_E + 8192 * 512) / 4;
    for (int i4 = blockIdx.x * blockDim.x + threadIdx.x; i4 < TOT4; i4 += gridDim.x * blockDim.x) {
        int e0 = i4 * 4;
        float4 x;
        float m;
        __nv_bfloat16 *hiArr, *loArr;
        int dst;
        if (e0 < A_E) {
            x = *(const float4*)(A + e0);
            int row = e0 >> 9;
            m = int_elem_nonzero(tokw, row, tok64) ? 1.f : 0.f;
            hiArr = g_Ahi; loArr = g_Alo; dst = e0;
        } else {
            int eb = e0 - A_E;
            x = *(const float4*)(B + eb);
            int row = eb >> 9;
            m = int_elem_nonzero(mskw, row, msk64) ? 1.f : 0.f;
            hiArr = g_Bhi; loArr = g_Blo; dst = eb;
        }
        float v[4] = {x.x * m, x.y * m, x.z * m, x.w * m};
        __nv_bfloat16 h[4], l[4];
        #pragma unroll
        for (int k = 0; k < 4; k++) {
            h[k] = __float2bfloat16_rn(v[k]);
            l[k] = __float2bfloat16_rn(v[k] - __bfloat162float(h[k]));
        }
        __nv_bfloat162* hp = (__nv_bfloat162*)(hiArr + dst);
        __nv_bfloat162* lp = (__nv_bfloat162*)(loArr + dst);
        hp[0] = __nv_bfloat162(h[0], h[1]);
        hp[1] = __nv_bfloat162(h[2], h[3]);
        lp[0] = __nv_bfloat162(l[0], l[1]);
        lp[1] = __nv_bfloat162(l[2], l[3]);
    }
}

// ---------------------------------------------------------------------------
// GEMM: 128x128 tile/CTA, 256 threads (8 warps, 64x32 warp tiles).
// K=512 in 8 chunks of 64.  Double-buffered cp.async, SW128 swizzle
// (16B unit c stored at c ^ (r&7), rows of 64 bf16 = 128B).
// 3-term split: acc += Ahi*Bhi + Ahi*Blo + Alo*Bhi  (fp32 accum).
// Stage layout (64 KB): Ahi 16K | Alo 16K | Bhi 16K | Blo 16K.
// ---------------------------------------------------------------------------
#define AHI_OFF 0
#define ALO_OFF 16384
#define BHI_OFF 32768
#define BLO_OFF 49152
#define STAGE_BYTES 65536
#define GEMM_SMEM (2 * STAGE_BYTES)

__device__ __forceinline__ void issue_copies(uint32_t sb, int m0, int n0, int ck, int tid) {
    const char* sAh = (const char*)g_Ahi;
    const char* sAl = (const char*)g_Alo;
    const char* sBh = (const char*)g_Bhi;
    const char* sBl = (const char*)g_Blo;
    #pragma unroll
    for (int i = 0; i < 4; i++) {
        int u = tid + 256 * i, r = u >> 3, c = u & 7;
        uint32_t d = sb + AHI_OFF + (uint32_t)(r * 128 + ((c ^ (r & 7)) * 16));
        CP_ASYNC16(d, sAh + ((size_t)(m0 + r) * 512 + ck * 64 + c * 8) * 2);
    }
    #pragma unroll
    for (int i = 0; i < 4; i++) {
        int u = tid + 256 * i, r = u >> 3, c = u & 7;
        uint32_t d = sb + ALO_OFF + (uint32_t)(r * 128 + ((c ^ (r & 7)) * 16));
        CP_ASYNC16(d, sAl + ((size_t)(m0 + r) * 512 + ck * 64 + c * 8) * 2);
    }
    #pragma unroll
    for (int i = 0; i < 4; i++) {
        int u = tid + 256 * i, r = u >> 3, c = u & 7;
        uint32_t d = sb + BHI_OFF + (uint32_t)(r * 128 + ((c ^ (r & 7)) * 16));
        CP_ASYNC16(d, sBh + ((size_t)(n0 + r) * 512 + ck * 64 + c * 8) * 2);
    }
    #pragma unroll
    for (int i = 0; i < 4; i++) {
        int u = tid + 256 * i, r = u >> 3, c = u & 7;
        uint32_t d = sb + BLO_OFF + (uint32_t)(r * 128 + ((c ^ (r & 7)) * 16));
        CP_ASYNC16(d, sBl + ((size_t)(n0 + r) * 512 + ck * 64 + c * 8) * 2);
    }
}

__global__ void __launch_bounds__(256, 1)
gemm_kernel() {
    extern __shared__ __align__(1024) char dyn[];
    uint32_t base = smem_u32(dyn);

    int tid = threadIdx.x;
    int w = tid >> 5, lane = tid & 31;
    int wm = w >> 2, wn = w & 3;          // warp tile: rows wm*64, cols wn*32
    int q = lane >> 2, t4 = lane & 3;
    int m0 = blockIdx.y * 128, n0 = blockIdx.x * 128;

    float acc[4][4][4];                    // [mi][ni][e]
    #pragma unroll
    for (int i = 0; i < 4; i++)
        #pragma unroll
        for (int j = 0; j < 4; j++)
            #pragma unroll
            for (int e = 0; e < 4; e++) acc[i][j][e] = 0.f;

    // ldmatrix per-lane row/col selectors (swizzle: unit col ^ (l&7))
    int aRowL = lane & 15;                 // row within m16 tile
    int aColS = (lane >> 4) & 1;           // k8-half selector
    int bRowL = (lane & 7) + ((lane >> 4) << 3);  // row within n16 pair
    int bColS = (lane >> 3) & 1;

    // prologue
    issue_copies(base + 0 * STAGE_BYTES, m0, n0, 0, tid);
    CP_COMMIT();
    issue_copies(base + 1 * STAGE_BYTES, m0, n0, 1, tid);
    CP_COMMIT();

    for (int ck = 0; ck < 8; ck++) {
        uint32_t sb = base + (ck & 1) * STAGE_BYTES;
        if (ck < 7) { CP_WAIT1(); } else { CP_WAIT0(); }
        __syncthreads();

        #pragma unroll
        for (int ks = 0; ks < 4; ks++) {
            uint32_t aH[4][4], aL[4][4];
            #pragma unroll
            for (int mi = 0; mi < 4; mi++) {
                int row = wm * 64 + mi * 16 + aRowL;
                uint32_t su = (uint32_t)((ks * 2 + aColS) ^ (lane & 7)) * 16;
                uint32_t ah = sb + AHI_OFF + row * 128 + su;
                uint32_t al = sb + ALO_OFF + row * 128 + su;
                LDSM_X4(aH[mi][0], aH[mi][1], aH[mi][2], aH[mi][3], ah);
                LDSM_X4(aL[mi][0], aL[mi][1], aL[mi][2], aL[mi][3], al);
            }
            uint32_t bH[2][4], bL[2][4];
            #pragma unroll
            for (int nt = 0; nt < 2; nt++) {
                int row = wn * 32 + nt * 16 + bRowL;
                uint32_t su = (uint32_t)((ks * 2 + bColS) ^ (lane & 7)) * 16;
                uint32_t bh = sb + BHI_OFF + row * 128 + su;
                uint32_t bl = sb + BLO_OFF + row * 128 + su;
                LDSM_X4(bH[nt][0], bH[nt][1], bH[nt][2], bH[nt][3], bh);
                LDSM_X4(bL[nt][0], bL[nt][1], bL[nt][2], bL[nt][3], bl);
            }
            #pragma unroll
            for (int mi = 0; mi < 4; mi++)
                #pragma unroll
                for (int ni = 0; ni < 4; ni++) {
                    int nt = ni >> 1, hf = (ni & 1) * 2;
                    MMA_BF16(acc[mi][ni], aH[mi], bH[nt][hf], bH[nt][hf + 1]);
                    MMA_BF16(acc[mi][ni], aH[mi], bL[nt][hf], bL[nt][hf + 1]);
                    MMA_BF16(acc[mi][ni], aL[mi], bH[nt][hf], bH[nt][hf + 1]);
                }
        }
        __syncthreads();
        if (ck + 2 < 8) {
            issue_copies(sb, m0, n0, ck + 2, tid);
            CP_COMMIT();
        }
    }

    // ---------------- fused epilogue (registers -> smem reductions) ----------
    // acc element (mi,ni,e): row = wm*64+mi*16+q+(e>=2)*8, col = wn*32+ni*8+t4*2+(e&1)
    float* rowred = (float*)dyn;          // [128 rows][4 wn]
    float* colred = (float*)dyn + 512;    // [128 cols][4 a]   (a = wm*2 + asub)

    // row partial maxes over warp's 32 cols
    #pragma unroll
    for (int mi = 0; mi < 4; mi++) {
        #pragma unroll
        for (int rh = 0; rh < 2; rh++) {
            float m = fmaxf(acc[mi][0][rh * 2], acc[mi][0][rh * 2 + 1]);
            #pragma unroll
            for (int ni = 1; ni < 4; ni++)
                m = fmaxf(m, fmaxf(acc[mi][ni][rh * 2], acc[mi][ni][rh * 2 + 1]));
            m = fmaxf(m, __shfl_xor_sync(0xffffffffu, m, 1));
            m = fmaxf(m, __shfl_xor_sync(0xffffffffu, m, 2));
            if (t4 == 0) rowred[(wm * 64 + mi * 16 + q + rh * 8) * 4 + wn] = m;
        }
    }
    // col partial maxes over warp's 64 rows, split per 32-row a-group
    #pragma unroll
    for (int ni = 0; ni < 4; ni++) {
        #pragma unroll
        for (int cp = 0; cp < 2; cp++) {
            #pragma unroll
            for (int asub = 0; asub < 2; asub++) {
                float m = fmaxf(fmaxf(acc[asub * 2][ni][cp], acc[asub * 2][ni][cp + 2]),
                                fmaxf(acc[asub * 2 + 1][ni][cp], acc[asub * 2 + 1][ni][cp + 2]));
                m = fmaxf(m, __shfl_xor_sync(0xffffffffu, m, 4));
                m = fmaxf(m, __shfl_xor_sync(0xffffffffu, m, 8));
                m = fmaxf(m, __shfl_xor_sync(0xffffffffu, m, 16));
                if (q == 0) colred[(wn * 32 + ni * 8 + t4 * 2 + cp) * 4 + (wm * 2 + asub)] = m;
            }
        }
    }
    __syncthreads();

    // 8 (a,b) pairs, one warp each: weighted sums + score
    {
        int a = w >> 1, b = w & 1;
        int aG = blockIdx.y * 4 + a;
        int bG = blockIdx.x * 2 + b;
        float rf = fmaxf(rowred[(a * 32 + lane) * 4 + 2 * b],
                         rowred[(a * 32 + lane) * 4 + 2 * b + 1]);
        float val = rf * g_wA[aG * 32 + lane];
        val += colred[(b * 64 + lane) * 4 + a]      * g_wB[bG * 64 + lane];
        val += colred[(b * 64 + lane + 32) * 4 + a] * g_wB[bG * 64 + lane + 32];
        #pragma unroll
        for (int o = 16; o; o >>= 1) val += __shfl_xor_sync(0xffffffffu, val, o);
        if (lane == 0) g_score[aG * 128 + bG] = 0.5f * val;
    }
}

// ---------------------------------------------------------------------------
// loss
// ---------------------------------------------------------------------------
__global__ void loss_kernel(const float* __restrict__ temp, float* __restrict__ out) {
    __shared__ float red[256];
    int tid = threadIdx.x;
    float invT = 1.0f / temp[0];
    int i = tid & 127;
    bool isRow = tid < 128;
    float mx = NEG_BIG;
    for (int j = 0; j < 128; j++) {
        float x = (isRow ? g_score[i * 128 + j] : g_score[j * 128 + i]) * invT;
        mx = fmaxf(mx, x);
    }
    float s = 0.f;
    for (int j = 0; j < 128; j++) {
        float x = (isRow ? g_score[i * 128 + j] : g_score[j * 128 + i]) * invT;
        s += expf(x - mx);
    }
    float lse = mx + logf(s);
    float diag = g_score[i * 128 + i] * invT;
    red[tid] = lse - diag;
    __syncthreads();
    for (int o = 128; o; o >>= 1) {
        if (tid < o) red[tid] += red[tid + o];
        __syncthreads();
    }
    if (tid == 0) out[0] = red[0] / 256.f;
}

// ---------------------------------------------------------------------------
extern "C" void kernel_launch(void* const* d_in, const int* in_sizes, int n_in,
                              void* d_out, int out_size) {
    (void)out_size;
    int order[7];
    for (int i = 0; i < 7 && i < n_in; i++) order[i] = i;
    for (int i = 1; i < 7; i++) {
        int o = order[i];
        long long s = in_sizes[o];
        int j = i - 1;
        while (j >= 0 && (long long)in_sizes[order[j]] > s) { order[j + 1] = order[j]; j--; }
        order[j + 1] = o;
    }
    const float* temp  = (const float*)d_in[order[0]];
    const void*  q0    = d_in[order[1]];
    const void*  q1    = d_in[order[2]];
    const void*  r0    = d_in[order[3]];
    const void*  r1    = d_in[order[4]];
    const float* featA = (const float*)d_in[order[5]];
    const float* featB = (const float*)d_in[order[6]];
    float* out = (float*)d_out;

    static bool attrSet = false;
    if (!attrSet) {
        cudaFuncSetAttribute(gemm_kernel, cudaFuncAttributeMaxDynamicSharedMemorySize, GEMM_SMEM);
        attrSet = true;
    }

    prep_kernel<<<256, 64>>>(q0, q1, r0, r1);
    convert_kernel<<<1024, 256>>>(featA, featB, q0, q1, r0, r1);
    gemm_kernel<<<dim3(64, 32), 256, GEMM_SMEM>>>();
    loss_kernel<<<1, 256>>>(temp, out);
}

// round 6
// speedup vs baseline: 2.5063x; 1.0024x over previous
#include <cuda_runtime.h>
#include <cuda_bf16.h>
#include <math.h>
#include <stdint.h>

// ---------------------------------------------------------------------------
// B=128, T=32, V=64, D=512.  score[128][128].
// sm_100 BASELINE target: mma.sync bf16 + cp.async + ldmatrix.
//   prep+convert:  one kernel (blocks <1024 convert fp32->masked bf16 hi/lo;
//                  blocks >=1024 compute masked-softmax weights, sync-free)
//   gemm_kernel:   128x128 tile, 8 warps, m16n8k16 bf16 3-term split GEMM
//                  (term-major MMA order -> no accumulator RAW chains),
//                  fused row/col-max + weighted reductions -> score[a][b]
//   loss_kernel:   smem-staged /temp log-softmax diagonals -> scalar
// ---------------------------------------------------------------------------

#define NEG_BIG (-3.0e38f)

__device__ float g_wA[128 * 32];
__device__ float g_wB[128 * 64];
__device__ float g_score[128 * 128];

__device__ __nv_bfloat16 g_Ahi[4096 * 512];
__device__ __nv_bfloat16 g_Alo[4096 * 512];
__device__ __nv_bfloat16 g_Bhi[8192 * 512];
__device__ __nv_bfloat16 g_Blo[8192 * 512];

// ---------------- PTX helpers ----------------
__device__ __forceinline__ uint32_t smem_u32(const void* p) {
    uint32_t a;
    asm("{ .reg .u64 t; cvta.to.shared.u64 t, %1; cvt.u32.u64 %0, t; }" : "=r"(a) : "l"(p));
    return a;
}
#define CP_ASYNC16(dst, src) asm volatile("cp.async.cg.shared.global [%0], [%1], 16;" :: "r"(dst), "l"(src))
#define CP_COMMIT()          asm volatile("cp.async.commit_group;" ::: "memory")
#define CP_WAIT1()           asm volatile("cp.async.wait_group 1;" ::: "memory")
#define CP_WAIT0()           asm volatile("cp.async.wait_group 0;" ::: "memory")
#define LDSM_X4(r0, r1, r2, r3, addr) \
    asm volatile("ldmatrix.sync.aligned.m8n8.x4.shared.b16 {%0,%1,%2,%3}, [%4];" \
        : "=r"(r0), "=r"(r1), "=r"(r2), "=r"(r3) : "r"(addr))
#define MMA_BF16(d, a, b0, b1) \
    asm volatile("mma.sync.aligned.m16n8k16.row.col.f32.bf16.bf16.f32 " \
        "{%0,%1,%2,%3}, {%4,%5,%6,%7}, {%8,%9}, {%0,%1,%2,%3};" \
        : "+f"((d)[0]), "+f"((d)[1]), "+f"((d)[2]), "+f"((d)[3]) \
        : "r"((a)[0]), "r"((a)[1]), "r"((a)[2]), "r"((a)[3]), "r"(b0), "r"(b1))

// ---------------- input disambiguation ----------------
__device__ __forceinline__ bool looks_like_int_small(const unsigned* w, unsigned limit) {
    bool ok = true;
    #pragma unroll
    for (int i = 0; i < 8; i++) ok = ok && (w[i] <= limit);
    return ok;
}
__device__ __forceinline__ bool int_width64(const unsigned* w) {
    return (w[1] == 0u) && (w[3] == 0u) && (w[5] == 0u) && (w[7] == 0u);
}
__device__ __forceinline__ bool int_elem_nonzero(const unsigned* w, int i, bool w64) {
    return w64 ? ((w[2 * i] | w[2 * i + 1]) != 0u) : (w[i] != 0u);
}

// ---------------------------------------------------------------------------
// prep+convert merged.  Blocks [0,1024): convert.  Blocks [1024,1152): prep
// row blockIdx-1024 (warp 0 -> wA row, warp 1 -> wB row; no __syncthreads).
// ---------------------------------------------------------------------------
__global__ void __launch_bounds__(256)
prep_convert_kernel(const float* __restrict__ A, const float* __restrict__ B,
                    const void* q0, const void* q1, const void* r0, const void* r1) {
    bool q0_tok = looks_like_int_small((const unsigned*)q0, 99999u);
    const unsigned* tokw = (const unsigned*)(q0_tok ? q0 : q1);
    const float*    wtA  = (const float*)(q0_tok ? q1 : q0);
    bool tok64 = int_width64(tokw);
    bool r0_msk = looks_like_int_small((const unsigned*)r0, 1u);
    const unsigned* mskw = (const unsigned*)(r0_msk ? r0 : r1);
    const float*    wtB  = (const float*)(r0_msk ? r1 : r0);
    bool msk64 = int_width64(mskw);

    if (blockIdx.x >= 1024) {
        int row = blockIdx.x - 1024;          // 0..127
        int w = threadIdx.x >> 5, lane = threadIdx.x & 31;
        if (w == 0) {                          // wA row
            float m = int_elem_nonzero(tokw, row * 32 + lane, tok64) ? 1.f : 0.f;
            float x = (m > 0.f) ? wtA[row * 32 + lane] : NEG_BIG;
            float mx = x;
            #pragma unroll
            for (int o = 16; o; o >>= 1) mx = fmaxf(mx, __shfl_xor_sync(0xffffffffu, mx, o));
            float e = expf(x - mx), s = e;
            #pragma unroll
            for (int o = 16; o; o >>= 1) s += __shfl_xor_sync(0xffffffffu, s, o);
            g_wA[row * 32 + lane] = e / s;
        } else if (w == 1) {                   // wB row, 2 elems per lane
            float m0 = int_elem_nonzero(mskw, row * 64 + lane, msk64) ? 1.f : 0.f;
            float m1 = int_elem_nonzero(mskw, row * 64 + lane + 32, msk64) ? 1.f : 0.f;
            float x0 = (m0 > 0.f) ? wtB[row * 64 + lane] : NEG_BIG;
            float x1 = (m1 > 0.f) ? wtB[row * 64 + lane + 32] : NEG_BIG;
            float mx = fmaxf(x0, x1);
            #pragma unroll
            for (int o = 16; o; o >>= 1) mx = fmaxf(mx, __shfl_xor_sync(0xffffffffu, mx, o));
            float e0 = expf(x0 - mx), e1 = expf(x1 - mx);
            float s = e0 + e1;
            #pragma unroll
            for (int o = 16; o; o >>= 1) s += __shfl_xor_sync(0xffffffffu, s, o);
            g_wB[row * 64 + lane] = e0 / s;
            g_wB[row * 64 + lane + 32] = e1 / s;
        }
        return;
    }

    const int A_E = 4096 * 512;
    const int TOT4 = (A_E + 8192 * 512) / 4;
    for (int i4 = blockIdx.x * 256 + threadIdx.x; i4 < TOT4; i4 += 1024 * 256) {
        int e0 = i4 * 4;
        float4 x;
        float m;
        __nv_bfloat16 *hiArr, *loArr;
        int dst;
        if (e0 < A_E) {
            x = *(const float4*)(A + e0);
            int row = e0 >> 9;
            m = int_elem_nonzero(tokw, row, tok64) ? 1.f : 0.f;
            hiArr = g_Ahi; loArr = g_Alo; dst = e0;
        } else {
            int eb = e0 - A_E;
            x = *(const float4*)(B + eb);
            int row = eb >> 9;
            m = int_elem_nonzero(mskw, row, msk64) ? 1.f : 0.f;
            hiArr = g_Bhi; loArr = g_Blo; dst = eb;
        }
        float v[4] = {x.x * m, x.y * m, x.z * m, x.w * m};
        __nv_bfloat16 h[4], l[4];
        #pragma unroll
        for (int k = 0; k < 4; k++) {
            h[k] = __float2bfloat16_rn(v[k]);
            l[k] = __float2bfloat16_rn(v[k] - __bfloat162float(h[k]));
        }
        __nv_bfloat162* hp = (__nv_bfloat162*)(hiArr + dst);
        __nv_bfloat162* lp = (__nv_bfloat162*)(loArr + dst);
        hp[0] = __nv_bfloat162(h[0], h[1]);
        hp[1] = __nv_bfloat162(h[2], h[3]);
        lp[0] = __nv_bfloat162(l[0], l[1]);
        lp[1] = __nv_bfloat162(l[2], l[3]);
    }
}

// ---------------------------------------------------------------------------
// GEMM: 128x128 tile/CTA, 256 threads (8 warps, 64x32 warp tiles).
// K=512 in 8 chunks of 64.  Double-buffered cp.async, SW128 swizzle.
// 3-term split, TERM-MAJOR: aH*bH (16 MMAs) ; aH*bL ; aL*bH  -> no acc chains.
// ---------------------------------------------------------------------------
#define AHI_OFF 0
#define ALO_OFF 16384
#define BHI_OFF 32768
#define BLO_OFF 49152
#define STAGE_BYTES 65536
#define GEMM_SMEM (2 * STAGE_BYTES)

__device__ __forceinline__ void issue_copies(uint32_t sb, int m0, int n0, int ck, int tid) {
    const char* sAh = (const char*)g_Ahi;
    const char* sAl = (const char*)g_Alo;
    const char* sBh = (const char*)g_Bhi;
    const char* sBl = (const char*)g_Blo;
    #pragma unroll
    for (int i = 0; i < 4; i++) {
        int u = tid + 256 * i, r = u >> 3, c = u & 7;
        uint32_t d = sb + AHI_OFF + (uint32_t)(r * 128 + ((c ^ (r & 7)) * 16));
        CP_ASYNC16(d, sAh + ((size_t)(m0 + r) * 512 + ck * 64 + c * 8) * 2);
    }
    #pragma unroll
    for (int i = 0; i < 4; i++) {
        int u = tid + 256 * i, r = u >> 3, c = u & 7;
        uint32_t d = sb + ALO_OFF + (uint32_t)(r * 128 + ((c ^ (r & 7)) * 16));
        CP_ASYNC16(d, sAl + ((size_t)(m0 + r) * 512 + ck * 64 + c * 8) * 2);
    }
    #pragma unroll
    for (int i = 0; i < 4; i++) {
        int u = tid + 256 * i, r = u >> 3, c = u & 7;
        uint32_t d = sb + BHI_OFF + (uint32_t)(r * 128 + ((c ^ (r & 7)) * 16));
        CP_ASYNC16(d, sBh + ((size_t)(n0 + r) * 512 + ck * 64 + c * 8) * 2);
    }
    #pragma unroll
    for (int i = 0; i < 4; i++) {
        int u = tid + 256 * i, r = u >> 3, c = u & 7;
        uint32_t d = sb + BLO_OFF + (uint32_t)(r * 128 + ((c ^ (r & 7)) * 16));
        CP_ASYNC16(d, sBl + ((size_t)(n0 + r) * 512 + ck * 64 + c * 8) * 2);
    }
}

__global__ void __launch_bounds__(256, 1)
gemm_kernel() {
    extern __shared__ __align__(1024) char dyn[];
    uint32_t base = smem_u32(dyn);

    int tid = threadIdx.x;
    int w = tid >> 5, lane = tid & 31;
    int wm = w >> 2, wn = w & 3;
    int q = lane >> 2, t4 = lane & 3;
    int m0 = blockIdx.y * 128, n0 = blockIdx.x * 128;

    float acc[4][4][4];
    #pragma unroll
    for (int i = 0; i < 4; i++)
        #pragma unroll
        for (int j = 0; j < 4; j++)
            #pragma unroll
            for (int e = 0; e < 4; e++) acc[i][j][e] = 0.f;

    int aRowL = lane & 15;
    int aColS = (lane >> 4) & 1;
    int bRowL = (lane & 7) + ((lane >> 4) << 3);
    int bColS = (lane >> 3) & 1;

    issue_copies(base + 0 * STAGE_BYTES, m0, n0, 0, tid);
    CP_COMMIT();
    issue_copies(base + 1 * STAGE_BYTES, m0, n0, 1, tid);
    CP_COMMIT();

    for (int ck = 0; ck < 8; ck++) {
        uint32_t sb = base + (ck & 1) * STAGE_BYTES;
        if (ck < 7) { CP_WAIT1(); } else { CP_WAIT0(); }
        __syncthreads();

        #pragma unroll
        for (int ks = 0; ks < 4; ks++) {
            uint32_t aH[4][4], aL[4][4];
            #pragma unroll
            for (int mi = 0; mi < 4; mi++) {
                int row = wm * 64 + mi * 16 + aRowL;
                uint32_t su = (uint32_t)((ks * 2 + aColS) ^ (lane & 7)) * 16;
                uint32_t ah = sb + AHI_OFF + row * 128 + su;
                uint32_t al = sb + ALO_OFF + row * 128 + su;
                LDSM_X4(aH[mi][0], aH[mi][1], aH[mi][2], aH[mi][3], ah);
                LDSM_X4(aL[mi][0], aL[mi][1], aL[mi][2], aL[mi][3], al);
            }
            uint32_t bH[2][4], bL[2][4];
            #pragma unroll
            for (int nt = 0; nt < 2; nt++) {
                int row = wn * 32 + nt * 16 + bRowL;
                uint32_t su = (uint32_t)((ks * 2 + bColS) ^ (lane & 7)) * 16;
                uint32_t bh = sb + BHI_OFF + row * 128 + su;
                uint32_t bl = sb + BLO_OFF + row * 128 + su;
                LDSM_X4(bH[nt][0], bH[nt][1], bH[nt][2], bH[nt][3], bh);
                LDSM_X4(bL[nt][0], bL[nt][1], bL[nt][2], bL[nt][3], bl);
            }
            // term-major: 16 independent MMAs between accumulator reuses
            #pragma unroll
            for (int mi = 0; mi < 4; mi++)
                #pragma unroll
                for (int ni = 0; ni < 4; ni++) {
                    int nt = ni >> 1, hf = (ni & 1) * 2;
                    MMA_BF16(acc[mi][ni], aH[mi], bH[nt][hf], bH[nt][hf + 1]);
                }
            #pragma unroll
            for (int mi = 0; mi < 4; mi++)
                #pragma unroll
                for (int ni = 0; ni < 4; ni++) {
                    int nt = ni >> 1, hf = (ni & 1) * 2;
                    MMA_BF16(acc[mi][ni], aH[mi], bL[nt][hf], bL[nt][hf + 1]);
                }
            #pragma unroll
            for (int mi = 0; mi < 4; mi++)
                #pragma unroll
                for (int ni = 0; ni < 4; ni++) {
                    int nt = ni >> 1, hf = (ni & 1) * 2;
                    MMA_BF16(acc[mi][ni], aL[mi], bH[nt][hf], bH[nt][hf + 1]);
                }
        }
        __syncthreads();
        if (ck + 2 < 8) {
            issue_copies(sb, m0, n0, ck + 2, tid);
            CP_COMMIT();
        }
    }

    // ---------------- fused epilogue ----------------
    float* rowred = (float*)dyn;          // [128 rows][4 wn]
    float* colred = (float*)dyn + 512;    // [128 cols][4 a]

    #pragma unroll
    for (int mi = 0; mi < 4; mi++) {
        #pragma unroll
        for (int rh = 0; rh < 2; rh++) {
            float m = fmaxf(acc[mi][0][rh * 2], acc[mi][0][rh * 2 + 1]);
            #pragma unroll
            for (int ni = 1; ni < 4; ni++)
                m = fmaxf(m, fmaxf(acc[mi][ni][rh * 2], acc[mi][ni][rh * 2 + 1]));
            m = fmaxf(m, __shfl_xor_sync(0xffffffffu, m, 1));
            m = fmaxf(m, __shfl_xor_sync(0xffffffffu, m, 2));
            if (t4 == 0) rowred[(wm * 64 + mi * 16 + q + rh * 8) * 4 + wn] = m;
        }
    }
    #pragma unroll
    for (int ni = 0; ni < 4; ni++) {
        #pragma unroll
        for (int cp = 0; cp < 2; cp++) {
            #pragma unroll
            for (int asub = 0; asub < 2; asub++) {
                float m = fmaxf(fmaxf(acc[asub * 2][ni][cp], acc[asub * 2][ni][cp + 2]),
                                fmaxf(acc[asub * 2 + 1][ni][cp], acc[asub * 2 + 1][ni][cp + 2]));
                m = fmaxf(m, __shfl_xor_sync(0xffffffffu, m, 4));
                m = fmaxf(m, __shfl_xor_sync(0xffffffffu, m, 8));
                m = fmaxf(m, __shfl_xor_sync(0xffffffffu, m, 16));
                if (q == 0) colred[(wn * 32 + ni * 8 + t4 * 2 + cp) * 4 + (wm * 2 + asub)] = m;
            }
        }
    }
    __syncthreads();

    {
        int a = w >> 1, b = w & 1;
        int aG = blockIdx.y * 4 + a;
        int bG = blockIdx.x * 2 + b;
        float rf = fmaxf(rowred[(a * 32 + lane) * 4 + 2 * b],
                         rowred[(a * 32 + lane) * 4 + 2 * b + 1]);
        float val = rf * g_wA[aG * 32 + lane];
        val += colred[(b * 64 + lane) * 4 + a]      * g_wB[bG * 64 + lane];
        val += colred[(b * 64 + lane + 32) * 4 + a] * g_wB[bG * 64 + lane + 32];
        #pragma unroll
        for (int o = 16; o; o >>= 1) val += __shfl_xor_sync(0xffffffffu, val, o);
        if (lane == 0) g_score[aG * 128 + bG] = 0.5f * val;
    }
}

// ---------------------------------------------------------------------------
// loss: smem-staged.  Coalesced load of the 64KB score matrix, then
// threads 0..127 row log-softmax, 128..255 col, all from smem.
// ---------------------------------------------------------------------------
#define LOSS_SMEM (16384 * 4 + 256 * 4)
__global__ void loss_kernel(const float* __restrict__ temp, float* __restrict__ out) {
    extern __shared__ __align__(16) float ls[];     // [16384] scores + [256] red
    float* red = ls + 16384;
    int tid = threadIdx.x;
    float invT = 1.0f / temp[0];

    float4* d4 = (float4*)ls;
    const float4* s4 = (const float4*)g_score;
    for (int i = tid; i < 4096; i += 256) d4[i] = s4[i];
    __syncthreads();

    int i = tid & 127;
    bool isRow = tid < 128;
    float mx = NEG_BIG;
    #pragma unroll 4
    for (int j = 0; j < 128; j++) {
        float x = isRow ? ls[i * 128 + j] : ls[j * 128 + i];
        mx = fmaxf(mx, x);
    }
    float s = 0.f;
    #pragma unroll 4
    for (int j = 0; j < 128; j++) {
        float x = isRow ? ls[i * 128 + j] : ls[j * 128 + i];
        s += expf((x - mx) * invT);
    }
    float lse = mx * invT + logf(s);
    float diag = ls[i * 128 + i] * invT;
    red[tid] = lse - diag;
    __syncthreads();
    for (int o = 128; o; o >>= 1) {
        if (tid < o) red[tid] += red[tid + o];
        __syncthreads();
    }
    if (tid == 0) out[0] = red[0] / 256.f;
}

// ---------------------------------------------------------------------------
extern "C" void kernel_launch(void* const* d_in, const int* in_sizes, int n_in,
                              void* d_out, int out_size) {
    (void)out_size;
    int order[7];
    for (int i = 0; i < 7 && i < n_in; i++) order[i] = i;
    for (int i = 1; i < 7; i++) {
        int o = order[i];
        long long s = in_sizes[o];
        int j = i - 1;
        while (j >= 0 && (long long)in_sizes[order[j]] > s) { order[j + 1] = order[j]; j--; }
        order[j + 1] = o;
    }
    const float* temp  = (const float*)d_in[order[0]];
    const void*  q0    = d_in[order[1]];
    const void*  q1    = d_in[order[2]];
    const void*  r0    = d_in[order[3]];
    const void*  r1    = d_in[order[4]];
    const float* featA = (const float*)d_in[order[5]];
    const float* featB = (const float*)d_in[order[6]];
    float* out = (float*)d_out;

    static bool attrSet = false;
    if (!attrSet) {
        cudaFuncSetAttribute(gemm_kernel, cudaFuncAttributeMaxDynamicSharedMemorySize, GEMM_SMEM);
        cudaFuncSetAttribute(loss_kernel, cudaFuncAttributeMaxDynamicSharedMemorySize, LOSS_SMEM);
        attrSet = true;
    }

    prep_convert_kernel<<<1152, 256>>>(featA, featB, q0, q1, r0, r1);
    gemm_kernel<<<dim3(64, 32), 256, GEMM_SMEM>>>();
    loss_kernel<<<1, 256, LOSS_SMEM>>>(temp, out);
}

// round 7
// speedup vs baseline: 2.5239x; 1.0070x over previous
#include <cuda_runtime.h>
#include <cuda_bf16.h>
#include <math.h>
#include <stdint.h>

// ---------------------------------------------------------------------------
// B=128, T=32, V=64, D=512.  score[128][128].
// sm_100 BASELINE target: mma.sync bf16 + cp.async + ldmatrix.
//   prep_convert:  blocks <1024 convert fp32->masked bf16 hi/lo;
//                  blocks >=1024 masked-softmax weights (sync-free)
//   gemm_kernel:   128x128 tile, 8 warps, m16n8k16 bf16 3-term split GEMM,
//                  3-stage cp.async pipeline (ONE barrier per K-chunk),
//                  fused row/col-max + weighted reductions -> score[a][b]
//   loss_kernel:   smem-staged /temp log-softmax diagonals -> scalar
// ---------------------------------------------------------------------------

#define NEG_BIG (-3.0e38f)

__device__ float g_wA[128 * 32];
__device__ float g_wB[128 * 64];
__device__ float g_score[128 * 128];

__device__ __nv_bfloat16 g_Ahi[4096 * 512];
__device__ __nv_bfloat16 g_Alo[4096 * 512];
__device__ __nv_bfloat16 g_Bhi[8192 * 512];
__device__ __nv_bfloat16 g_Blo[8192 * 512];

// ---------------- PTX helpers ----------------
__device__ __forceinline__ uint32_t smem_u32(const void* p) {
    uint32_t a;
    asm("{ .reg .u64 t; cvta.to.shared.u64 t, %1; cvt.u32.u64 %0, t; }" : "=r"(a) : "l"(p));
    return a;
}
#define CP_ASYNC16(dst, src) asm volatile("cp.async.cg.shared.global [%0], [%1], 16;" :: "r"(dst), "l"(src))
#define CP_COMMIT()          asm volatile("cp.async.commit_group;" ::: "memory")
#define CP_WAIT1()           asm volatile("cp.async.wait_group 1;" ::: "memory")
#define CP_WAIT0()           asm volatile("cp.async.wait_group 0;" ::: "memory")
#define LDSM_X4(r0, r1, r2, r3, addr) \
    asm volatile("ldmatrix.sync.aligned.m8n8.x4.shared.b16 {%0,%1,%2,%3}, [%4];" \
        : "=r"(r0), "=r"(r1), "=r"(r2), "=r"(r3) : "r"(addr))
#define MMA_BF16(d, a, b0, b1) \
    asm volatile("mma.sync.aligned.m16n8k16.row.col.f32.bf16.bf16.f32 " \
        "{%0,%1,%2,%3}, {%4,%5,%6,%7}, {%8,%9}, {%0,%1,%2,%3};" \
        : "+f"((d)[0]), "+f"((d)[1]), "+f"((d)[2]), "+f"((d)[3]) \
        : "r"((a)[0]), "r"((a)[1]), "r"((a)[2]), "r"((a)[3]), "r"(b0), "r"(b1))

// ---------------- input disambiguation ----------------
__device__ __forceinline__ bool looks_like_int_small(const unsigned* w, unsigned limit) {
    bool ok = true;
    #pragma unroll
    for (int i = 0; i < 8; i++) ok = ok && (w[i] <= limit);
    return ok;
}
__device__ __forceinline__ bool int_width64(const unsigned* w) {
    return (w[1] == 0u) && (w[3] == 0u) && (w[5] == 0u) && (w[7] == 0u);
}
__device__ __forceinline__ bool int_elem_nonzero(const unsigned* w, int i, bool w64) {
    return w64 ? ((w[2 * i] | w[2 * i + 1]) != 0u) : (w[i] != 0u);
}

// ---------------------------------------------------------------------------
// prep+convert merged.
// ---------------------------------------------------------------------------
__global__ void __launch_bounds__(256)
prep_convert_kernel(const float* __restrict__ A, const float* __restrict__ B,
                    const void* q0, const void* q1, const void* r0, const void* r1) {
    bool q0_tok = looks_like_int_small((const unsigned*)q0, 99999u);
    const unsigned* tokw = (const unsigned*)(q0_tok ? q0 : q1);
    const float*    wtA  = (const float*)(q0_tok ? q1 : q0);
    bool tok64 = int_width64(tokw);
    bool r0_msk = looks_like_int_small((const unsigned*)r0, 1u);
    const unsigned* mskw = (const unsigned*)(r0_msk ? r0 : r1);
    const float*    wtB  = (const float*)(r0_msk ? r1 : r0);
    bool msk64 = int_width64(mskw);

    if (blockIdx.x >= 1024) {
        int row = blockIdx.x - 1024;
        int w = threadIdx.x >> 5, lane = threadIdx.x & 31;
        if (w == 0) {
            float m = int_elem_nonzero(tokw, row * 32 + lane, tok64) ? 1.f : 0.f;
            float x = (m > 0.f) ? wtA[row * 32 + lane] : NEG_BIG;
            float mx = x;
            #pragma unroll
            for (int o = 16; o; o >>= 1) mx = fmaxf(mx, __shfl_xor_sync(0xffffffffu, mx, o));
            float e = expf(x - mx), s = e;
            #pragma unroll
            for (int o = 16; o; o >>= 1) s += __shfl_xor_sync(0xffffffffu, s, o);
            g_wA[row * 32 + lane] = e / s;
        } else if (w == 1) {
            float m0 = int_elem_nonzero(mskw, row * 64 + lane, msk64) ? 1.f : 0.f;
            float m1 = int_elem_nonzero(mskw, row * 64 + lane + 32, msk64) ? 1.f : 0.f;
            float x0 = (m0 > 0.f) ? wtB[row * 64 + lane] : NEG_BIG;
            float x1 = (m1 > 0.f) ? wtB[row * 64 + lane + 32] : NEG_BIG;
            float mx = fmaxf(x0, x1);
            #pragma unroll
            for (int o = 16; o; o >>= 1) mx = fmaxf(mx, __shfl_xor_sync(0xffffffffu, mx, o));
            float e0 = expf(x0 - mx), e1 = expf(x1 - mx);
            float s = e0 + e1;
            #pragma unroll
            for (int o = 16; o; o >>= 1) s += __shfl_xor_sync(0xffffffffu, s, o);
            g_wB[row * 64 + lane] = e0 / s;
            g_wB[row * 64 + lane + 32] = e1 / s;
        }
        return;
    }

    const int A_E = 4096 * 512;
    const int TOT4 = (A_E + 8192 * 512) / 4;
    for (int i4 = blockIdx.x * 256 + threadIdx.x; i4 < TOT4; i4 += 1024 * 256) {
        int e0 = i4 * 4;
        float4 x;
        float m;
        __nv_bfloat16 *hiArr, *loArr;
        int dst;
        if (e0 < A_E) {
            x = *(const float4*)(A + e0);
            int row = e0 >> 9;
            m = int_elem_nonzero(tokw, row, tok64) ? 1.f : 0.f;
            hiArr = g_Ahi; loArr = g_Alo; dst = e0;
        } else {
            int eb = e0 - A_E;
            x = *(const float4*)(B + eb);
            int row = eb >> 9;
            m = int_elem_nonzero(mskw, row, msk64) ? 1.f : 0.f;
            hiArr = g_Bhi; loArr = g_Blo; dst = eb;
        }
        float v[4] = {x.x * m, x.y * m, x.z * m, x.w * m};
        __nv_bfloat16 h[4], l[4];
        #pragma unroll
        for (int k = 0; k < 4; k++) {
            h[k] = __float2bfloat16_rn(v[k]);
            l[k] = __float2bfloat16_rn(v[k] - __bfloat162float(h[k]));
        }
        __nv_bfloat162* hp = (__nv_bfloat162*)(hiArr + dst);
        __nv_bfloat162* lp = (__nv_bfloat162*)(loArr + dst);
        hp[0] = __nv_bfloat162(h[0], h[1]);
        hp[1] = __nv_bfloat162(h[2], h[3]);
        lp[0] = __nv_bfloat162(l[0], l[1]);
        lp[1] = __nv_bfloat162(l[2], l[3]);
    }
}

// ---------------------------------------------------------------------------
// GEMM: 128x128 tile/CTA, 256 threads (8 warps, 64x32 warp tiles).
// K=512 in 8 chunks of 64.  THREE-stage cp.async pipeline, SW128 swizzle.
// Per chunk: wait(ck) -> sync -> issue(ck+2) -> compute(ck).  One barrier.
// 3-term split, interleaved per-(mi,ni) (empirically fastest ordering).
// ---------------------------------------------------------------------------
#define AHI_OFF 0
#define ALO_OFF 16384
#define BHI_OFF 32768
#define BLO_OFF 49152
#define STAGE_BYTES 65536
#define GEMM_SMEM (3 * STAGE_BYTES)

__device__ __forceinline__ void issue_copies(uint32_t sb, int m0, int n0, int ck, int tid) {
    const char* sAh = (const char*)g_Ahi;
    const char* sAl = (const char*)g_Alo;
    const char* sBh = (const char*)g_Bhi;
    const char* sBl = (const char*)g_Blo;
    #pragma unroll
    for (int i = 0; i < 4; i++) {
        int u = tid + 256 * i, r = u >> 3, c = u & 7;
        uint32_t d = sb + AHI_OFF + (uint32_t)(r * 128 + ((c ^ (r & 7)) * 16));
        CP_ASYNC16(d, sAh + ((size_t)(m0 + r) * 512 + ck * 64 + c * 8) * 2);
    }
    #pragma unroll
    for (int i = 0; i < 4; i++) {
        int u = tid + 256 * i, r = u >> 3, c = u & 7;
        uint32_t d = sb + ALO_OFF + (uint32_t)(r * 128 + ((c ^ (r & 7)) * 16));
        CP_ASYNC16(d, sAl + ((size_t)(m0 + r) * 512 + ck * 64 + c * 8) * 2);
    }
    #pragma unroll
    for (int i = 0; i < 4; i++) {
        int u = tid + 256 * i, r = u >> 3, c = u & 7;
        uint32_t d = sb + BHI_OFF + (uint32_t)(r * 128 + ((c ^ (r & 7)) * 16));
        CP_ASYNC16(d, sBh + ((size_t)(n0 + r) * 512 + ck * 64 + c * 8) * 2);
    }
    #pragma unroll
    for (int i = 0; i < 4; i++) {
        int u = tid + 256 * i, r = u >> 3, c = u & 7;
        uint32_t d = sb + BLO_OFF + (uint32_t)(r * 128 + ((c ^ (r & 7)) * 16));
        CP_ASYNC16(d, sBl + ((size_t)(n0 + r) * 512 + ck * 64 + c * 8) * 2);
    }
}

__global__ void __launch_bounds__(256, 1)
gemm_kernel() {
    extern __shared__ __align__(1024) char dyn[];
    uint32_t base = smem_u32(dyn);

    int tid = threadIdx.x;
    int w = tid >> 5, lane = tid & 31;
    int wm = w >> 2, wn = w & 3;
    int q = lane >> 2, t4 = lane & 3;
    int m0 = blockIdx.y * 128, n0 = blockIdx.x * 128;

    float acc[4][4][4];
    #pragma unroll
    for (int i = 0; i < 4; i++)
        #pragma unroll
        for (int j = 0; j < 4; j++)
            #pragma unroll
            for (int e = 0; e < 4; e++) acc[i][j][e] = 0.f;

    int aRowL = lane & 15;
    int aColS = (lane >> 4) & 1;
    int bRowL = (lane & 7) + ((lane >> 4) << 3);
    int bColS = (lane >> 3) & 1;

    // prologue: stages 0,1 hold chunks 0,1
    issue_copies(base + 0 * STAGE_BYTES, m0, n0, 0, tid);
    CP_COMMIT();
    issue_copies(base + 1 * STAGE_BYTES, m0, n0, 1, tid);
    CP_COMMIT();

    for (int ck = 0; ck < 8; ck++) {
        uint32_t sb = base + (uint32_t)(ck % 3) * STAGE_BYTES;
        if (ck < 7) { CP_WAIT1(); } else { CP_WAIT0(); }
        __syncthreads();
        // issue chunk ck+2 into stage (ck+2)%3 == (ck-1)%3: all warps finished
        // chunk ck-1 before this barrier, so that stage is free.
        if (ck + 2 < 8) {
            issue_copies(base + (uint32_t)((ck + 2) % 3) * STAGE_BYTES, m0, n0, ck + 2, tid);
            CP_COMMIT();
        }

        #pragma unroll
        for (int ks = 0; ks < 4; ks++) {
            uint32_t aH[4][4], aL[4][4];
            #pragma unroll
            for (int mi = 0; mi < 4; mi++) {
                int row = wm * 64 + mi * 16 + aRowL;
                uint32_t su = (uint32_t)((ks * 2 + aColS) ^ (lane & 7)) * 16;
                uint32_t ah = sb + AHI_OFF + row * 128 + su;
                uint32_t al = sb + ALO_OFF + row * 128 + su;
                LDSM_X4(aH[mi][0], aH[mi][1], aH[mi][2], aH[mi][3], ah);
                LDSM_X4(aL[mi][0], aL[mi][1], aL[mi][2], aL[mi][3], al);
            }
            uint32_t bH[2][4], bL[2][4];
            #pragma unroll
            for (int nt = 0; nt < 2; nt++) {
                int row = wn * 32 + nt * 16 + bRowL;
                uint32_t su = (uint32_t)((ks * 2 + bColS) ^ (lane & 7)) * 16;
                uint32_t bh = sb + BHI_OFF + row * 128 + su;
                uint32_t bl = sb + BLO_OFF + row * 128 + su;
                LDSM_X4(bH[nt][0], bH[nt][1], bH[nt][2], bH[nt][3], bh);
                LDSM_X4(bL[nt][0], bL[nt][1], bL[nt][2], bL[nt][3], bl);
            }
            #pragma unroll
            for (int mi = 0; mi < 4; mi++)
                #pragma unroll
                for (int ni = 0; ni < 4; ni++) {
                    int nt = ni >> 1, hf = (ni & 1) * 2;
                    MMA_BF16(acc[mi][ni], aH[mi], bH[nt][hf], bH[nt][hf + 1]);
                    MMA_BF16(acc[mi][ni], aH[mi], bL[nt][hf], bL[nt][hf + 1]);
                    MMA_BF16(acc[mi][ni], aL[mi], bH[nt][hf], bH[nt][hf + 1]);
                }
        }
    }
    __syncthreads();  // stage smem dead; safe to reuse for reductions

    // ---------------- fused epilogue ----------------
    float* rowred = (float*)dyn;          // [128 rows][4 wn]
    float* colred = (float*)dyn + 512;    // [128 cols][4 a]

    #pragma unroll
    for (int mi = 0; mi < 4; mi++) {
        #pragma unroll
        for (int rh = 0; rh < 2; rh++) {
            float m = fmaxf(acc[mi][0][rh * 2], acc[mi][0][rh * 2 + 1]);
            #pragma unroll
            for (int ni = 1; ni < 4; ni++)
                m = fmaxf(m, fmaxf(acc[mi][ni][rh * 2], acc[mi][ni][rh * 2 + 1]));
            m = fmaxf(m, __shfl_xor_sync(0xffffffffu, m, 1));
            m = fmaxf(m, __shfl_xor_sync(0xffffffffu, m, 2));
            if (t4 == 0) rowred[(wm * 64 + mi * 16 + q + rh * 8) * 4 + wn] = m;
        }
    }
    #pragma unroll
    for (int ni = 0; ni < 4; ni++) {
        #pragma unroll
        for (int cp = 0; cp < 2; cp++) {
            #pragma unroll
            for (int asub = 0; asub < 2; asub++) {
                float m = fmaxf(fmaxf(acc[asub * 2][ni][cp], acc[asub * 2][ni][cp + 2]),
                                fmaxf(acc[asub * 2 + 1][ni][cp], acc[asub * 2 + 1][ni][cp + 2]));
                m = fmaxf(m, __shfl_xor_sync(0xffffffffu, m, 4));
                m = fmaxf(m, __shfl_xor_sync(0xffffffffu, m, 8));
                m = fmaxf(m, __shfl_xor_sync(0xffffffffu, m, 16));
                if (q == 0) colred[(wn * 32 + ni * 8 + t4 * 2 + cp) * 4 + (wm * 2 + asub)] = m;
            }
        }
    }
    __syncthreads();

    {
        int a = w >> 1, b = w & 1;
        int aG = blockIdx.y * 4 + a;
        int bG = blockIdx.x * 2 + b;
        float rf = fmaxf(rowred[(a * 32 + lane) * 4 + 2 * b],
                         rowred[(a * 32 + lane) * 4 + 2 * b + 1]);
        float val = rf * g_wA[aG * 32 + lane];
        val += colred[(b * 64 + lane) * 4 + a]      * g_wB[bG * 64 + lane];
        val += colred[(b * 64 + lane + 32) * 4 + a] * g_wB[bG * 64 + lane + 32];
        #pragma unroll
        for (int o = 16; o; o >>= 1) val += __shfl_xor_sync(0xffffffffu, val, o);
        if (lane == 0) g_score[aG * 128 + bG] = 0.5f * val;
    }
}

// ---------------------------------------------------------------------------
// loss: smem-staged.
// ---------------------------------------------------------------------------
#define LOSS_SMEM (16384 * 4 + 256 * 4)
__global__ void loss_kernel(const float* __restrict__ temp, float* __restrict__ out) {
    extern __shared__ __align__(16) float ls[];
    float* red = ls + 16384;
    int tid = threadIdx.x;
    float invT = 1.0f / temp[0];

    float4* d4 = (float4*)ls;
    const float4* s4 = (const float4*)g_score;
    for (int i = tid; i < 4096; i += 256) d4[i] = s4[i];
    __syncthreads();

    int i = tid & 127;
    bool isRow = tid < 128;
    float mx = NEG_BIG;
    #pragma unroll 4
    for (int j = 0; j < 128; j++) {
        float x = isRow ? ls[i * 128 + j] : ls[j * 128 + i];
        mx = fmaxf(mx, x);
    }
    float s = 0.f;
    #pragma unroll 4
    for (int j = 0; j < 128; j++) {
        float x = isRow ? ls[i * 128 + j] : ls[j * 128 + i];
        s += expf((x - mx) * invT);
    }
    float lse = mx * invT + logf(s);
    float diag = ls[i * 128 + i] * invT;
    red[tid] = lse - diag;
    __syncthreads();
    for (int o = 128; o; o >>= 1) {
        if (tid < o) red[tid] += red[tid + o];
        __syncthreads();
    }
    if (tid == 0) out[0] = red[0] / 256.f;
}

// ---------------------------------------------------------------------------
extern "C" void kernel_launch(void* const* d_in, const int* in_sizes, int n_in,
                              void* d_out, int out_size) {
    (void)out_size;
    int order[7];
    for (int i = 0; i < 7 && i < n_in; i++) order[i] = i;
    for (int i = 1; i < 7; i++) {
        int o = order[i];
        long long s = in_sizes[o];
        int j = i - 1;
        while (j >= 0 && (long long)in_sizes[order[j]] > s) { order[j + 1] = order[j]; j--; }
        order[j + 1] = o;
    }
    const float* temp  = (const float*)d_in[order[0]];
    const void*  q0    = d_in[order[1]];
    const void*  q1    = d_in[order[2]];
    const void*  r0    = d_in[order[3]];
    const void*  r1    = d_in[order[4]];
    const float* featA = (const float*)d_in[order[5]];
    const float* featB = (const float*)d_in[order[6]];
    float* out = (float*)d_out;

    static bool attrSet = false;
    if (!attrSet) {
        cudaFuncSetAttribute(gemm_kernel, cudaFuncAttributeMaxDynamicSharedMemorySize, GEMM_SMEM);
        cudaFuncSetAttribute(loss_kernel, cudaFuncAttributeMaxDynamicSharedMemorySize, LOSS_SMEM);
        attrSet = true;
    }

    prep_convert_kernel<<<1152, 256>>>(featA, featB, q0, q1, r0, r1);
    gemm_kernel<<<dim3(64, 32), 256, GEMM_SMEM>>>();
    loss_kernel<<<1, 256, LOSS_SMEM>>>(temp, out);
}

// round 8
// speedup vs baseline: 2.5895x; 1.0260x over previous
#include <cuda_runtime.h>
#include <cuda_bf16.h>
#include <math.h>
#include <stdint.h>

// ---------------------------------------------------------------------------
// B=128, T=32, V=64, D=512.  score[128][128].
// sm_100 BASELINE target: mma.sync bf16 + cp.async + ldmatrix.
//   prep_convert:  blocks <1024 convert fp32->masked bf16 hi/lo;
//                  blocks >=1024 masked-softmax weights (sync-free)
//   gemm_kernel:   128x64 tile/CTA, 2 CTAs/SM (96KB smem, <=128 regs),
//                  8 warps (32x32 tiles), m16n8k16 bf16 3-term split GEMM,
//                  2-stage cp.async pipeline, fused row/col-max + weighted
//                  reductions -> score[a][b]
//   loss_kernel:   smem-staged /temp log-softmax diagonals -> scalar
// ---------------------------------------------------------------------------

#define NEG_BIG (-3.0e38f)

__device__ float g_wA[128 * 32];
__device__ float g_wB[128 * 64];
__device__ float g_score[128 * 128];

__device__ __nv_bfloat16 g_Ahi[4096 * 512];
__device__ __nv_bfloat16 g_Alo[4096 * 512];
__device__ __nv_bfloat16 g_Bhi[8192 * 512];
__device__ __nv_bfloat16 g_Blo[8192 * 512];

// ---------------- PTX helpers ----------------
__device__ __forceinline__ uint32_t smem_u32(const void* p) {
    uint32_t a;
    asm("{ .reg .u64 t; cvta.to.shared.u64 t, %1; cvt.u32.u64 %0, t; }" : "=r"(a) : "l"(p));
    return a;
}
#define CP_ASYNC16(dst, src) asm volatile("cp.async.cg.shared.global [%0], [%1], 16;" :: "r"(dst), "l"(src))
#define CP_COMMIT()          asm volatile("cp.async.commit_group;" ::: "memory")
#define CP_WAIT1()           asm volatile("cp.async.wait_group 1;" ::: "memory")
#define CP_WAIT0()           asm volatile("cp.async.wait_group 0;" ::: "memory")
#define LDSM_X4(r0, r1, r2, r3, addr) \
    asm volatile("ldmatrix.sync.aligned.m8n8.x4.shared.b16 {%0,%1,%2,%3}, [%4];" \
        : "=r"(r0), "=r"(r1), "=r"(r2), "=r"(r3) : "r"(addr))
#define MMA_BF16(d, a, b0, b1) \
    asm volatile("mma.sync.aligned.m16n8k16.row.col.f32.bf16.bf16.f32 " \
        "{%0,%1,%2,%3}, {%4,%5,%6,%7}, {%8,%9}, {%0,%1,%2,%3};" \
        : "+f"((d)[0]), "+f"((d)[1]), "+f"((d)[2]), "+f"((d)[3]) \
        : "r"((a)[0]), "r"((a)[1]), "r"((a)[2]), "r"((a)[3]), "r"(b0), "r"(b1))

// ---------------- input disambiguation ----------------
__device__ __forceinline__ bool looks_like_int_small(const unsigned* w, unsigned limit) {
    bool ok = true;
    #pragma unroll
    for (int i = 0; i < 8; i++) ok = ok && (w[i] <= limit);
    return ok;
}
__device__ __forceinline__ bool int_width64(const unsigned* w) {
    return (w[1] == 0u) && (w[3] == 0u) && (w[5] == 0u) && (w[7] == 0u);
}
__device__ __forceinline__ bool int_elem_nonzero(const unsigned* w, int i, bool w64) {
    return w64 ? ((w[2 * i] | w[2 * i + 1]) != 0u) : (w[i] != 0u);
}

// ---------------------------------------------------------------------------
// prep+convert merged.
// ---------------------------------------------------------------------------
__global__ void __launch_bounds__(256)
prep_convert_kernel(const float* __restrict__ A, const float* __restrict__ B,
                    const void* q0, const void* q1, const void* r0, const void* r1) {
    bool q0_tok = looks_like_int_small((const unsigned*)q0, 99999u);
    const unsigned* tokw = (const unsigned*)(q0_tok ? q0 : q1);
    const float*    wtA  = (const float*)(q0_tok ? q1 : q0);
    bool tok64 = int_width64(tokw);
    bool r0_msk = looks_like_int_small((const unsigned*)r0, 1u);
    const unsigned* mskw = (const unsigned*)(r0_msk ? r0 : r1);
    const float*    wtB  = (const float*)(r0_msk ? r1 : r0);
    bool msk64 = int_width64(mskw);

    if (blockIdx.x >= 1024) {
        int row = blockIdx.x - 1024;
        int w = threadIdx.x >> 5, lane = threadIdx.x & 31;
        if (w == 0) {
            float m = int_elem_nonzero(tokw, row * 32 + lane, tok64) ? 1.f : 0.f;
            float x = (m > 0.f) ? wtA[row * 32 + lane] : NEG_BIG;
            float mx = x;
            #pragma unroll
            for (int o = 16; o; o >>= 1) mx = fmaxf(mx, __shfl_xor_sync(0xffffffffu, mx, o));
            float e = expf(x - mx), s = e;
            #pragma unroll
            for (int o = 16; o; o >>= 1) s += __shfl_xor_sync(0xffffffffu, s, o);
            g_wA[row * 32 + lane] = e / s;
        } else if (w == 1) {
            float m0 = int_elem_nonzero(mskw, row * 64 + lane, msk64) ? 1.f : 0.f;
            float m1 = int_elem_nonzero(mskw, row * 64 + lane + 32, msk64) ? 1.f : 0.f;
            float x0 = (m0 > 0.f) ? wtB[row * 64 + lane] : NEG_BIG;
            float x1 = (m1 > 0.f) ? wtB[row * 64 + lane + 32] : NEG_BIG;
            float mx = fmaxf(x0, x1);
            #pragma unroll
            for (int o = 16; o; o >>= 1) mx = fmaxf(mx, __shfl_xor_sync(0xffffffffu, mx, o));
            float e0 = expf(x0 - mx), e1 = expf(x1 - mx);
            float s = e0 + e1;
            #pragma unroll
            for (int o = 16; o; o >>= 1) s += __shfl_xor_sync(0xffffffffu, s, o);
            g_wB[row * 64 + lane] = e0 / s;
            g_wB[row * 64 + lane + 32] = e1 / s;
        }
        return;
    }

    const int A_E = 4096 * 512;
    const int TOT4 = (A_E + 8192 * 512) / 4;
    for (int i4 = blockIdx.x * 256 + threadIdx.x; i4 < TOT4; i4 += 1024 * 256) {
        int e0 = i4 * 4;
        float4 x;
        float m;
        __nv_bfloat16 *hiArr, *loArr;
        int dst;
        if (e0 < A_E) {
            x = *(const float4*)(A + e0);
            int row = e0 >> 9;
            m = int_elem_nonzero(tokw, row, tok64) ? 1.f : 0.f;
            hiArr = g_Ahi; loArr = g_Alo; dst = e0;
        } else {
            int eb = e0 - A_E;
            x = *(const float4*)(B + eb);
            int row = eb >> 9;
            m = int_elem_nonzero(mskw, row, msk64) ? 1.f : 0.f;
            hiArr = g_Bhi; loArr = g_Blo; dst = eb;
        }
        float v[4] = {x.x * m, x.y * m, x.z * m, x.w * m};
        __nv_bfloat16 h[4], l[4];
        #pragma unroll
        for (int k = 0; k < 4; k++) {
            h[k] = __float2bfloat16_rn(v[k]);
            l[k] = __float2bfloat16_rn(v[k] - __bfloat162float(h[k]));
        }
        __nv_bfloat162* hp = (__nv_bfloat162*)(hiArr + dst);
        __nv_bfloat162* lp = (__nv_bfloat162*)(loArr + dst);
        hp[0] = __nv_bfloat162(h[0], h[1]);
        hp[1] = __nv_bfloat162(h[2], h[3]);
        lp[0] = __nv_bfloat162(l[0], l[1]);
        lp[1] = __nv_bfloat162(l[2], l[3]);
    }
}

// ---------------------------------------------------------------------------
// GEMM: 128x64 tile/CTA, 2 CTAs/SM.  256 threads, 8 warps = 4 row-bands x
// 2 col-bands, warp tile 32x32.  K=512 in 8 chunks of 64.  2-stage cp.async.
// Stage (48 KB): Ahi 16K | Alo 16K | Bhi 8K | Blo 8K.
// ---------------------------------------------------------------------------
#define AHI_OFF 0
#define ALO_OFF 16384
#define BHI_OFF 32768
#define BLO_OFF 40960
#define STAGE_BYTES 49152
#define GEMM_SMEM (2 * STAGE_BYTES)

__device__ __forceinline__ void issue_copies(uint32_t sb, int m0, int n0, int ck, int tid) {
    const char* sAh = (const char*)g_Ahi;
    const char* sAl = (const char*)g_Alo;
    const char* sBh = (const char*)g_Bhi;
    const char* sBl = (const char*)g_Blo;
    #pragma unroll
    for (int i = 0; i < 4; i++) {              // Ahi: 128 rows x 8 units
        int u = tid + 256 * i, r = u >> 3, c = u & 7;
        uint32_t d = sb + AHI_OFF + (uint32_t)(r * 128 + ((c ^ (r & 7)) * 16));
        CP_ASYNC16(d, sAh + ((size_t)(m0 + r) * 512 + ck * 64 + c * 8) * 2);
    }
    #pragma unroll
    for (int i = 0; i < 4; i++) {              // Alo
        int u = tid + 256 * i, r = u >> 3, c = u & 7;
        uint32_t d = sb + ALO_OFF + (uint32_t)(r * 128 + ((c ^ (r & 7)) * 16));
        CP_ASYNC16(d, sAl + ((size_t)(m0 + r) * 512 + ck * 64 + c * 8) * 2);
    }
    #pragma unroll
    for (int i = 0; i < 2; i++) {              // Bhi: 64 rows x 8 units
        int u = tid + 256 * i, r = u >> 3, c = u & 7;
        uint32_t d = sb + BHI_OFF + (uint32_t)(r * 128 + ((c ^ (r & 7)) * 16));
        CP_ASYNC16(d, sBh + ((size_t)(n0 + r) * 512 + ck * 64 + c * 8) * 2);
    }
    #pragma unroll
    for (int i = 0; i < 2; i++) {              // Blo
        int u = tid + 256 * i, r = u >> 3, c = u & 7;
        uint32_t d = sb + BLO_OFF + (uint32_t)(r * 128 + ((c ^ (r & 7)) * 16));
        CP_ASYNC16(d, sBl + ((size_t)(n0 + r) * 512 + ck * 64 + c * 8) * 2);
    }
}

__global__ void __launch_bounds__(256, 2)
gemm_kernel() {
    extern __shared__ __align__(1024) char dyn[];
    uint32_t base = smem_u32(dyn);

    int tid = threadIdx.x;
    int w = tid >> 5, lane = tid & 31;
    int wm = w >> 1, wn = w & 1;               // 4 row-bands x 2 col-bands
    int q = lane >> 2, t4 = lane & 3;
    int m0 = blockIdx.y * 128, n0 = blockIdx.x * 64;

    float acc[2][4][4];                         // [mi][ni][e], warp tile 32x32
    #pragma unroll
    for (int i = 0; i < 2; i++)
        #pragma unroll
        for (int j = 0; j < 4; j++)
            #pragma unroll
            for (int e = 0; e < 4; e++) acc[i][j][e] = 0.f;

    int aRowL = lane & 15;
    int aColS = (lane >> 4) & 1;
    int bRowL = (lane & 7) + ((lane >> 4) << 3);
    int bColS = (lane >> 3) & 1;

    issue_copies(base + 0 * STAGE_BYTES, m0, n0, 0, tid);
    CP_COMMIT();
    issue_copies(base + 1 * STAGE_BYTES, m0, n0, 1, tid);
    CP_COMMIT();

    for (int ck = 0; ck < 8; ck++) {
        uint32_t sb = base + (uint32_t)(ck & 1) * STAGE_BYTES;
        if (ck < 7) { CP_WAIT1(); } else { CP_WAIT0(); }
        __syncthreads();

        #pragma unroll
        for (int ks = 0; ks < 4; ks++) {
            uint32_t aH[2][4], aL[2][4];
            #pragma unroll
            for (int mi = 0; mi < 2; mi++) {
                int row = wm * 32 + mi * 16 + aRowL;
                uint32_t su = (uint32_t)((ks * 2 + aColS) ^ (lane & 7)) * 16;
                LDSM_X4(aH[mi][0], aH[mi][1], aH[mi][2], aH[mi][3], sb + AHI_OFF + row * 128 + su);
                LDSM_X4(aL[mi][0], aL[mi][1], aL[mi][2], aL[mi][3], sb + ALO_OFF + row * 128 + su);
            }
            uint32_t bH[2][4], bL[2][4];
            #pragma unroll
            for (int nt = 0; nt < 2; nt++) {
                int row = wn * 32 + nt * 16 + bRowL;
                uint32_t su = (uint32_t)((ks * 2 + bColS) ^ (lane & 7)) * 16;
                LDSM_X4(bH[nt][0], bH[nt][1], bH[nt][2], bH[nt][3], sb + BHI_OFF + row * 128 + su);
                LDSM_X4(bL[nt][0], bL[nt][1], bL[nt][2], bL[nt][3], sb + BLO_OFF + row * 128 + su);
            }
            #pragma unroll
            for (int mi = 0; mi < 2; mi++)
                #pragma unroll
                for (int ni = 0; ni < 4; ni++) {
                    int nt = ni >> 1, hf = (ni & 1) * 2;
                    MMA_BF16(acc[mi][ni], aH[mi], bH[nt][hf], bH[nt][hf + 1]);
                    MMA_BF16(acc[mi][ni], aH[mi], bL[nt][hf], bL[nt][hf + 1]);
                    MMA_BF16(acc[mi][ni], aL[mi], bH[nt][hf], bH[nt][hf + 1]);
                }
        }
        __syncthreads();
        if (ck + 2 < 8) {
            issue_copies(sb, m0, n0, ck + 2, tid);
            CP_COMMIT();
        }
    }

    // ---------------- fused epilogue ----------------
    // acc (mi,ni,e): row = wm*32 + mi*16 + q + (e>=2)*8,
    //                col = wn*32 + ni*8 + t4*2 + (e&1)
    float* rowred = (float*)dyn;          // [128 rows][2 wn]   = 256 floats
    float* colred = (float*)dyn + 256;    // [64 cols][4 a]     = 256 floats

    // row partial maxes over warp's 32 cols
    #pragma unroll
    for (int mi = 0; mi < 2; mi++) {
        #pragma unroll
        for (int rh = 0; rh < 2; rh++) {
            float m = fmaxf(acc[mi][0][rh * 2], acc[mi][0][rh * 2 + 1]);
            #pragma unroll
            for (int ni = 1; ni < 4; ni++)
                m = fmaxf(m, fmaxf(acc[mi][ni][rh * 2], acc[mi][ni][rh * 2 + 1]));
            m = fmaxf(m, __shfl_xor_sync(0xffffffffu, m, 1));
            m = fmaxf(m, __shfl_xor_sync(0xffffffffu, m, 2));
            if (t4 == 0) rowred[(wm * 32 + mi * 16 + q + rh * 8) * 2 + wn] = m;
        }
    }
    // col maxes over warp's 32 rows (= exactly text a-group wm)
    #pragma unroll
    for (int ni = 0; ni < 4; ni++) {
        #pragma unroll
        for (int cp = 0; cp < 2; cp++) {
            float m = fmaxf(fmaxf(acc[0][ni][cp], acc[0][ni][cp + 2]),
                            fmaxf(acc[1][ni][cp], acc[1][ni][cp + 2]));
            m = fmaxf(m, __shfl_xor_sync(0xffffffffu, m, 4));
            m = fmaxf(m, __shfl_xor_sync(0xffffffffu, m, 8));
            m = fmaxf(m, __shfl_xor_sync(0xffffffffu, m, 16));
            if (q == 0) colred[(wn * 32 + ni * 8 + t4 * 2 + cp) * 4 + wm] = m;
        }
    }
    __syncthreads();

    // 4 (a) pairs vs the single 64-col b; warps 0..3 handle a = w
    if (w < 4) {
        int a = w;
        int aG = blockIdx.y * 4 + a;
        int bG = blockIdx.x;                 // 64-col tile == one video b
        float rf = fmaxf(rowred[(a * 32 + lane) * 2 + 0],
                         rowred[(a * 32 + lane) * 2 + 1]);
        float val = rf * g_wA[aG * 32 + lane];
        val += colred[lane * 4 + a]        * g_wB[bG * 64 + lane];
        val += colred[(lane + 32) * 4 + a] * g_wB[bG * 64 + lane + 32];
        #pragma unroll
        for (int o = 16; o; o >>= 1) val += __shfl_xor_sync(0xffffffffu, val, o);
        if (lane == 0) g_score[aG * 128 + bG] = 0.5f * val;
    }
}

// ---------------------------------------------------------------------------
// loss: smem-staged.
// ---------------------------------------------------------------------------
#define LOSS_SMEM (16384 * 4 + 256 * 4)
__global__ void loss_kernel(const float* __restrict__ temp, float* __restrict__ out) {
    extern __shared__ __align__(16) float ls[];
    float* red = ls + 16384;
    int tid = threadIdx.x;
    float invT = 1.0f / temp[0];

    float4* d4 = (float4*)ls;
    const float4* s4 = (const float4*)g_score;
    for (int i = tid; i < 4096; i += 256) d4[i] = s4[i];
    __syncthreads();

    int i = tid & 127;
    bool isRow = tid < 128;
    float mx = NEG_BIG;
    #pragma unroll 4
    for (int j = 0; j < 128; j++) {
        float x = isRow ? ls[i * 128 + j] : ls[j * 128 + i];
        mx = fmaxf(mx, x);
    }
    float s = 0.f;
    #pragma unroll 4
    for (int j = 0; j < 128; j++) {
        float x = isRow ? ls[i * 128 + j] : ls[j * 128 + i];
        s += expf((x - mx) * invT);
    }
    float lse = mx * invT + logf(s);
    float diag = ls[i * 128 + i] * invT;
    red[tid] = lse - diag;
    __syncthreads();
    for (int o = 128; o; o >>= 1) {
        if (tid < o) red[tid] += red[tid + o];
        __syncthreads();
    }
    if (tid == 0) out[0] = red[0] / 256.f;
}

// ---------------------------------------------------------------------------
extern "C" void kernel_launch(void* const* d_in, const int* in_sizes, int n_in,
                              void* d_out, int out_size) {
    (void)out_size;
    int order[7];
    for (int i = 0; i < 7 && i < n_in; i++) order[i] = i;
    for (int i = 1; i < 7; i++) {
        int o = order[i];
        long long s = in_sizes[o];
        int j = i - 1;
        while (j >= 0 && (long long)in_sizes[order[j]] > s) { order[j + 1] = order[j]; j--; }
        order[j + 1] = o;
    }
    const float* temp  = (const float*)d_in[order[0]];
    const void*  q0    = d_in[order[1]];
    const void*  q1    = d_in[order[2]];
    const void*  r0    = d_in[order[3]];
    const void*  r1    = d_in[order[4]];
    const float* featA = (const float*)d_in[order[5]];
    const float* featB = (const float*)d_in[order[6]];
    float* out = (float*)d_out;

    static bool attrSet = false;
    if (!attrSet) {
        cudaFuncSetAttribute(gemm_kernel, cudaFuncAttributeMaxDynamicSharedMemorySize, GEMM_SMEM);
        cudaFuncSetAttribute(loss_kernel, cudaFuncAttributeMaxDynamicSharedMemorySize, LOSS_SMEM);
        attrSet = true;
    }

    prep_convert_kernel<<<1152, 256>>>(featA, featB, q0, q1, r0, r1);
    gemm_kernel<<<dim3(128, 32), 256, GEMM_SMEM>>>();
    loss_kernel<<<1, 256, LOSS_SMEM>>>(temp, out);
}

// round 9
// speedup vs baseline: 4.0035x; 1.5461x over previous
#include <cuda_runtime.h>
#include <math.h>
#include <stdint.h>

// ---------------------------------------------------------------------------
// B=128, T=32, V=64, D=512.  score[128][128].
// sm_100 BASELINE target: mma.sync s8 (m16n8k32) + cp.async + ldmatrix.
// 2-level int8 row-scaled split:  x = s*(q1 + q2/254) + O(s/508)
//   score = sA[r]*sB[c]*( Σq1a*q1b + (Σq1a*q2b + Σq2a*q1b)/254 )
//   quant_prep:  per-row amax+quantize to q1/q2 int8 + scales; softmax weights
//   gemm_kernel: 128x64 tile/CTA, 2 CTAs/SM, 8 warps (32x32), 2 s32 acc banks,
//                2-stage cp.async (K chunks of 128), fused scale+max epilogue
//   loss_kernel: smem-staged /temp log-softmax diagonals -> scalar
// ---------------------------------------------------------------------------

#define NEG_BIG (-3.0e38f)

__device__ float g_wA[128 * 32];
__device__ float g_wB[128 * 64];
__device__ float g_score[128 * 128];
__device__ float g_sA[4096];
__device__ float g_sB[8192];

// int8 split arrays, 16B-aligned for vector stores / cp.async
__device__ uint4 g_Aq1[4096 * 512 / 16];
__device__ uint4 g_Aq2[4096 * 512 / 16];
__device__ uint4 g_Bq1[8192 * 512 / 16];
__device__ uint4 g_Bq2[8192 * 512 / 16];

// ---------------- PTX helpers ----------------
__device__ __forceinline__ uint32_t smem_u32(const void* p) {
    uint32_t a;
    asm("{ .reg .u64 t; cvta.to.shared.u64 t, %1; cvt.u32.u64 %0, t; }" : "=r"(a) : "l"(p));
    return a;
}
#define CP_ASYNC16(dst, src) asm volatile("cp.async.cg.shared.global [%0], [%1], 16;" :: "r"(dst), "l"(src))
#define CP_COMMIT()          asm volatile("cp.async.commit_group;" ::: "memory")
#define CP_WAIT1()           asm volatile("cp.async.wait_group 1;" ::: "memory")
#define CP_WAIT0()           asm volatile("cp.async.wait_group 0;" ::: "memory")
#define LDSM_X4(r0, r1, r2, r3, addr) \
    asm volatile("ldmatrix.sync.aligned.m8n8.x4.shared.b16 {%0,%1,%2,%3}, [%4];" \
        : "=r"(r0), "=r"(r1), "=r"(r2), "=r"(r3) : "r"(addr))
#define MMA_S8(d, a, b0, b1) \
    asm volatile("mma.sync.aligned.m16n8k32.row.col.s32.s8.s8.s32 " \
        "{%0,%1,%2,%3}, {%4,%5,%6,%7}, {%8,%9}, {%0,%1,%2,%3};" \
        : "+r"((d)[0]), "+r"((d)[1]), "+r"((d)[2]), "+r"((d)[3]) \
        : "r"((a)[0]), "r"((a)[1]), "r"((a)[2]), "r"((a)[3]), "r"(b0), "r"(b1))

// ---------------- input disambiguation ----------------
__device__ __forceinline__ bool looks_like_int_small(const unsigned* w, unsigned limit) {
    bool ok = true;
    #pragma unroll
    for (int i = 0; i < 8; i++) ok = ok && (w[i] <= limit);
    return ok;
}
__device__ __forceinline__ bool int_width64(const unsigned* w) {
    return (w[1] == 0u) && (w[3] == 0u) && (w[5] == 0u) && (w[7] == 0u);
}
__device__ __forceinline__ bool int_elem_nonzero(const unsigned* w, int i, bool w64) {
    return w64 ? ((w[2 * i] | w[2 * i + 1]) != 0u) : (w[i] != 0u);
}

// ---------------------------------------------------------------------------
// quant + prep.  Blocks [0,1536): one warp per feature row (12288 rows),
// per-row amax -> s, q1, q2.  Blocks [1536,1664): masked-softmax weights.
// ---------------------------------------------------------------------------
__global__ void __launch_bounds__(256)
quant_prep_kernel(const float* __restrict__ A, const float* __restrict__ B,
                  const void* q0, const void* q1p, const void* r0, const void* r1) {
    bool q0_tok = looks_like_int_small((const unsigned*)q0, 99999u);
    const unsigned* tokw = (const unsigned*)(q0_tok ? q0 : q1p);
    const float*    wtA  = (const float*)(q0_tok ? q1p : q0);
    bool tok64 = int_width64(tokw);
    bool r0_msk = looks_like_int_small((const unsigned*)r0, 1u);
    const unsigned* mskw = (const unsigned*)(r0_msk ? r0 : r1);
    const float*    wtB  = (const float*)(r0_msk ? r1 : r0);
    bool msk64 = int_width64(mskw);

    if (blockIdx.x >= 1536) {      // softmax-weight blocks
        int row = blockIdx.x - 1536;
        int w = threadIdx.x >> 5, lane = threadIdx.x & 31;
        if (w == 0) {
            float m = int_elem_nonzero(tokw, row * 32 + lane, tok64) ? 1.f : 0.f;
            float x = (m > 0.f) ? wtA[row * 32 + lane] : NEG_BIG;
            float mx = x;
            #pragma unroll
            for (int o = 16; o; o >>= 1) mx = fmaxf(mx, __shfl_xor_sync(0xffffffffu, mx, o));
            float e = expf(x - mx), s = e;
            #pragma unroll
            for (int o = 16; o; o >>= 1) s += __shfl_xor_sync(0xffffffffu, s, o);
            g_wA[row * 32 + lane] = e / s;
        } else if (w == 1) {
            float m0 = int_elem_nonzero(mskw, row * 64 + lane, msk64) ? 1.f : 0.f;
            float m1 = int_elem_nonzero(mskw, row * 64 + lane + 32, msk64) ? 1.f : 0.f;
            float x0 = (m0 > 0.f) ? wtB[row * 64 + lane] : NEG_BIG;
            float x1 = (m1 > 0.f) ? wtB[row * 64 + lane + 32] : NEG_BIG;
            float mx = fmaxf(x0, x1);
            #pragma unroll
            for (int o = 16; o; o >>= 1) mx = fmaxf(mx, __shfl_xor_sync(0xffffffffu, mx, o));
            float e0 = expf(x0 - mx), e1 = expf(x1 - mx);
            float s = e0 + e1;
            #pragma unroll
            for (int o = 16; o; o >>= 1) s += __shfl_xor_sync(0xffffffffu, s, o);
            g_wB[row * 64 + lane] = e0 / s;
            g_wB[row * 64 + lane + 32] = e1 / s;
        }
        return;
    }

    // quant: one warp per row
    int w = threadIdx.x >> 5, lane = threadIdx.x & 31;
    int row = blockIdx.x * 8 + w;          // 0..12287
    bool isA = row < 4096;
    int rloc = isA ? row : row - 4096;
    const float* src = isA ? (A + (size_t)rloc * 512) : (B + (size_t)rloc * 512);
    float m = isA ? (int_elem_nonzero(tokw, rloc, tok64) ? 1.f : 0.f)
                  : (int_elem_nonzero(mskw, rloc, msk64) ? 1.f : 0.f);

    float v[16];
    #pragma unroll
    for (int i = 0; i < 4; i++) {
        float4 x = ((const float4*)src)[lane * 4 + i];
        v[i * 4 + 0] = x.x * m;
        v[i * 4 + 1] = x.y * m;
        v[i * 4 + 2] = x.z * m;
        v[i * 4 + 3] = x.w * m;
    }
    float amax = 0.f;
    #pragma unroll
    for (int i = 0; i < 16; i++) amax = fmaxf(amax, fabsf(v[i]));
    #pragma unroll
    for (int o = 16; o; o >>= 1) amax = fmaxf(amax, __shfl_xor_sync(0xffffffffu, amax, o));

    float sInv = (amax > 0.f) ? (127.f / amax) : 0.f;
    float s = amax * (1.f / 127.f);

    uint32_t p1[4], p2[4];
    #pragma unroll
    for (int g = 0; g < 4; g++) {
        uint32_t u1 = 0, u2 = 0;
        #pragma unroll
        for (int k = 0; k < 4; k++) {
            float x = v[g * 4 + k];
            float f1 = rintf(x * sInv);
            f1 = fminf(fmaxf(f1, -127.f), 127.f);
            int i1 = (int)f1;
            float r = fmaf(-f1, s, x);
            float f2 = rintf(r * 254.f * sInv);
            f2 = fminf(fmaxf(f2, -127.f), 127.f);
            int i2 = (int)f2;
            u1 |= ((uint32_t)(uint8_t)i1) << (k * 8);
            u2 |= ((uint32_t)(uint8_t)i2) << (k * 8);
        }
        p1[g] = u1; p2[g] = u2;
    }
    uint4 pk1 = make_uint4(p1[0], p1[1], p1[2], p1[3]);
    uint4 pk2 = make_uint4(p2[0], p2[1], p2[2], p2[3]);
    size_t idx = (size_t)rloc * 32 + lane;     // 512 bytes/row = 32 uint4
    if (isA) { g_Aq1[idx] = pk1; g_Aq2[idx] = pk2; }
    else     { g_Bq1[idx] = pk1; g_Bq2[idx] = pk2; }
    if (lane == 0) { if (isA) g_sA[rloc] = s; else g_sB[rloc] = s; }
}

// ---------------------------------------------------------------------------
// GEMM: 128x64 tile/CTA, 2 CTAs/SM.  256 threads, 8 warps = 4 row-bands x
// 2 col-bands (warp tile 32x32).  K=512 in 4 chunks of 128 int8 (128B rows,
// SW128 swizzle).  2-stage cp.async.  Stage (48 KB): AQ1 16K|AQ2 16K|BQ1 8K|BQ2 8K.
// ---------------------------------------------------------------------------
#define AQ1_OFF 0
#define AQ2_OFF 16384
#define BQ1_OFF 32768
#define BQ2_OFF 40960
#define STAGE_BYTES 49152
#define GEMM_SMEM (2 * STAGE_BYTES)

__device__ __forceinline__ void issue_copies(uint32_t sb, int m0, int n0, int ck, int tid) {
    const char* sA1 = (const char*)g_Aq1;
    const char* sA2 = (const char*)g_Aq2;
    const char* sB1 = (const char*)g_Bq1;
    const char* sB2 = (const char*)g_Bq2;
    #pragma unroll
    for (int i = 0; i < 4; i++) {              // AQ1: 128 rows x 8 units
        int u = tid + 256 * i, r = u >> 3, c = u & 7;
        uint32_t d = sb + AQ1_OFF + (uint32_t)(r * 128 + ((c ^ (r & 7)) * 16));
        CP_ASYNC16(d, sA1 + (size_t)(m0 + r) * 512 + ck * 128 + c * 16);
    }
    #pragma unroll
    for (int i = 0; i < 4; i++) {              // AQ2
        int u = tid + 256 * i, r = u >> 3, c = u & 7;
        uint32_t d = sb + AQ2_OFF + (uint32_t)(r * 128 + ((c ^ (r & 7)) * 16));
        CP_ASYNC16(d, sA2 + (size_t)(m0 + r) * 512 + ck * 128 + c * 16);
    }
    #pragma unroll
    for (int i = 0; i < 2; i++) {              // BQ1: 64 rows x 8 units
        int u = tid + 256 * i, r = u >> 3, c = u & 7;
        uint32_t d = sb + BQ1_OFF + (uint32_t)(r * 128 + ((c ^ (r & 7)) * 16));
        CP_ASYNC16(d, sB1 + (size_t)(n0 + r) * 512 + ck * 128 + c * 16);
    }
    #pragma unroll
    for (int i = 0; i < 2; i++) {              // BQ2
        int u = tid + 256 * i, r = u >> 3, c = u & 7;
        uint32_t d = sb + BQ2_OFF + (uint32_t)(r * 128 + ((c ^ (r & 7)) * 16));
        CP_ASYNC16(d, sB2 + (size_t)(n0 + r) * 512 + ck * 128 + c * 16);
    }
}

__global__ void __launch_bounds__(256, 2)
gemm_kernel() {
    extern __shared__ __align__(1024) char dyn[];
    uint32_t base = smem_u32(dyn);

    int tid = threadIdx.x;
    int w = tid >> 5, lane = tid & 31;
    int wm = w >> 1, wn = w & 1;               // 4 row-bands x 2 col-bands
    int q = lane >> 2, t4 = lane & 3;
    int m0 = blockIdx.y * 128, n0 = blockIdx.x * 64;

    int acc1[2][4][4], acc2[2][4][4];
    #pragma unroll
    for (int i = 0; i < 2; i++)
        #pragma unroll
        for (int j = 0; j < 4; j++)
            #pragma unroll
            for (int e = 0; e < 4; e++) { acc1[i][j][e] = 0; acc2[i][j][e] = 0; }

    issue_copies(base + 0 * STAGE_BYTES, m0, n0, 0, tid);
    CP_COMMIT();
    issue_copies(base + 1 * STAGE_BYTES, m0, n0, 1, tid);
    CP_COMMIT();

    // per-lane ldmatrix address components
    int aRow = wm * 32 + ((lane >> 3) & 1) * 8 + (lane & 7);  // + mi*16
    int aUsel = lane >> 4;                                     // k-unit select
    int bRow = wn * 32 + lane;                                 // n row

    for (int ck = 0; ck < 4; ck++) {
        uint32_t sb = base + (uint32_t)(ck & 1) * STAGE_BYTES;
        if (ck < 3) { CP_WAIT1(); } else { CP_WAIT0(); }
        __syncthreads();

        #pragma unroll
        for (int ks = 0; ks < 4; ks++) {
            int ub = ks * 2;
            uint32_t a1f[2][4], a2f[2][4];
            #pragma unroll
            for (int mi = 0; mi < 2; mi++) {
                int row = aRow + mi * 16;
                uint32_t su = (uint32_t)((ub + aUsel) ^ (row & 7)) * 16;
                uint32_t ad = sb + (uint32_t)(row * 128) + su;
                LDSM_X4(a1f[mi][0], a1f[mi][1], a1f[mi][2], a1f[mi][3], ad + AQ1_OFF);
                LDSM_X4(a2f[mi][0], a2f[mi][1], a2f[mi][2], a2f[mi][3], ad + AQ2_OFF);
            }
            uint32_t b1u0[4], b1u1[4], b2u0[4], b2u1[4];
            {
                uint32_t su0 = (uint32_t)(ub ^ (lane & 7)) * 16;
                uint32_t su1 = (uint32_t)((ub + 1) ^ (lane & 7)) * 16;
                uint32_t bd = sb + (uint32_t)(bRow * 128);
                LDSM_X4(b1u0[0], b1u0[1], b1u0[2], b1u0[3], bd + BQ1_OFF + su0);
                LDSM_X4(b1u1[0], b1u1[1], b1u1[2], b1u1[3], bd + BQ1_OFF + su1);
                LDSM_X4(b2u0[0], b2u0[1], b2u0[2], b2u0[3], bd + BQ2_OFF + su0);
                LDSM_X4(b2u1[0], b2u1[1], b2u1[2], b2u1[3], bd + BQ2_OFF + su1);
            }
            #pragma unroll
            for (int mi = 0; mi < 2; mi++)
                #pragma unroll
                for (int j = 0; j < 4; j++) {
                    MMA_S8(acc1[mi][j], a1f[mi], b1u0[j], b1u1[j]);
                    MMA_S8(acc2[mi][j], a1f[mi], b2u0[j], b2u1[j]);
                    MMA_S8(acc2[mi][j], a2f[mi], b1u0[j], b1u1[j]);
                }
        }
        __syncthreads();
        if (ck + 2 < 4) {
            issue_copies(sb, m0, n0, ck + 2, tid);
            CP_COMMIT();
        }
    }

    // ---------------- fused epilogue (scales + max reductions) ----------------
    // element (mi,j,e): row = wm*32+mi*16+q+(e>>1)*8, col = wn*32+j*8+t4*2+(e&1)
    const float inv254 = 1.f / 254.f;
    float sAv[2][2];
    #pragma unroll
    for (int mi = 0; mi < 2; mi++)
        #pragma unroll
        for (int rh = 0; rh < 2; rh++)
            sAv[mi][rh] = g_sA[m0 + wm * 32 + mi * 16 + q + rh * 8];
    float sBv[4][2];
    #pragma unroll
    for (int j = 0; j < 4; j++)
        #pragma unroll
        for (int cp = 0; cp < 2; cp++)
            sBv[j][cp] = g_sB[n0 + wn * 32 + j * 8 + t4 * 2 + cp];

    float sc[2][4][4];
    #pragma unroll
    for (int mi = 0; mi < 2; mi++)
        #pragma unroll
        for (int j = 0; j < 4; j++)
            #pragma unroll
            for (int e = 0; e < 4; e++) {
                float v = __int2float_rn(acc1[mi][j][e]) + __int2float_rn(acc2[mi][j][e]) * inv254;
                sc[mi][j][e] = sAv[mi][e >> 1] * sBv[j][e & 1] * v;
            }

    float* rowred = (float*)dyn;          // [128 rows][2 wn]
    float* colred = (float*)dyn + 256;    // [64 cols][4 a]

    #pragma unroll
    for (int mi = 0; mi < 2; mi++) {
        #pragma unroll
        for (int rh = 0; rh < 2; rh++) {
            float m = fmaxf(sc[mi][0][rh * 2], sc[mi][0][rh * 2 + 1]);
            #pragma unroll
            for (int j = 1; j < 4; j++)
                m = fmaxf(m, fmaxf(sc[mi][j][rh * 2], sc[mi][j][rh * 2 + 1]));
            m = fmaxf(m, __shfl_xor_sync(0xffffffffu, m, 1));
            m = fmaxf(m, __shfl_xor_sync(0xffffffffu, m, 2));
            if (t4 == 0) rowred[(wm * 32 + mi * 16 + q + rh * 8) * 2 + wn] = m;
        }
    }
    #pragma unroll
    for (int j = 0; j < 4; j++) {
        #pragma unroll
        for (int cp = 0; cp < 2; cp++) {
            float m = fmaxf(fmaxf(sc[0][j][cp], sc[0][j][cp + 2]),
                            fmaxf(sc[1][j][cp], sc[1][j][cp + 2]));
            m = fmaxf(m, __shfl_xor_sync(0xffffffffu, m, 4));
            m = fmaxf(m, __shfl_xor_sync(0xffffffffu, m, 8));
            m = fmaxf(m, __shfl_xor_sync(0xffffffffu, m, 16));
            if (q == 0) colred[(wn * 32 + j * 8 + t4 * 2 + cp) * 4 + wm] = m;
        }
    }
    __syncthreads();

    if (w < 4) {
        int a = w;
        int aG = blockIdx.y * 4 + a;
        int bG = blockIdx.x;
        float rf = fmaxf(rowred[(a * 32 + lane) * 2 + 0],
                         rowred[(a * 32 + lane) * 2 + 1]);
        float val = rf * g_wA[aG * 32 + lane];
        val += colred[lane * 4 + a]        * g_wB[bG * 64 + lane];
        val += colred[(lane + 32) * 4 + a] * g_wB[bG * 64 + lane + 32];
        #pragma unroll
        for (int o = 16; o; o >>= 1) val += __shfl_xor_sync(0xffffffffu, val, o);
        if (lane == 0) g_score[aG * 128 + bG] = 0.5f * val;
    }
}

// ---------------------------------------------------------------------------
// loss: smem-staged.
// ---------------------------------------------------------------------------
#define LOSS_SMEM (16384 * 4 + 256 * 4)
__global__ void loss_kernel(const float* __restrict__ temp, float* __restrict__ out) {
    extern __shared__ __align__(16) float ls[];
    float* red = ls + 16384;
    int tid = threadIdx.x;
    float invT = 1.0f / temp[0];

    float4* d4 = (float4*)ls;
    const float4* s4 = (const float4*)g_score;
    for (int i = tid; i < 4096; i += 256) d4[i] = s4[i];
    __syncthreads();

    int i = tid & 127;
    bool isRow = tid < 128;
    float mx = NEG_BIG;
    #pragma unroll 4
    for (int j = 0; j < 128; j++) {
        float x = isRow ? ls[i * 128 + j] : ls[j * 128 + i];
        mx = fmaxf(mx, x);
    }
    float s = 0.f;
    #pragma unroll 4
    for (int j = 0; j < 128; j++) {
        float x = isRow ? ls[i * 128 + j] : ls[j * 128 + i];
        s += expf((x - mx) * invT);
    }
    float lse = mx * invT + logf(s);
    float diag = ls[i * 128 + i] * invT;
    red[tid] = lse - diag;
    __syncthreads();
    for (int o = 128; o; o >>= 1) {
        if (tid < o) red[tid] += red[tid + o];
        __syncthreads();
    }
    if (tid == 0) out[0] = red[0] / 256.f;
}

// ---------------------------------------------------------------------------
extern "C" void kernel_launch(void* const* d_in, const int* in_sizes, int n_in,
                              void* d_out, int out_size) {
    (void)out_size;
    int order[7];
    for (int i = 0; i < 7 && i < n_in; i++) order[i] = i;
    for (int i = 1; i < 7; i++) {
        int o = order[i];
        long long s = in_sizes[o];
        int j = i - 1;
        while (j >= 0 && (long long)in_sizes[order[j]] > s) { order[j + 1] = order[j]; j--; }
        order[j + 1] = o;
    }
    const float* temp  = (const float*)d_in[order[0]];
    const void*  q0    = d_in[order[1]];
    const void*  q1    = d_in[order[2]];
    const void*  r0    = d_in[order[3]];
    const void*  r1    = d_in[order[4]];
    const float* featA = (const float*)d_in[order[5]];
    const float* featB = (const float*)d_in[order[6]];
    float* out = (float*)d_out;

    static bool attrSet = false;
    if (!attrSet) {
        cudaFuncSetAttribute(gemm_kernel, cudaFuncAttributeMaxDynamicSharedMemorySize, GEMM_SMEM);
        cudaFuncSetAttribute(loss_kernel, cudaFuncAttributeMaxDynamicSharedMemorySize, LOSS_SMEM);
        attrSet = true;
    }

    quant_prep_kernel<<<1664, 256>>>(featA, featB, q0, q1, r0, r1);
    gemm_kernel<<<dim3(128, 32), 256, GEMM_SMEM>>>();
    loss_kernel<<<1, 256, LOSS_SMEM>>>(temp, out);
}